// round 11
// baseline (speedup 1.0000x reference)
#include <cuda_runtime.h>

#define NB 64
#define NT 256
#define BT (NB*NT)
#define BNS 0.9999950000374997f

__constant__ int c_s2j[25] = {0,1,2,3,20, 4,5,6,7,21,22, 8,9,10,11,23,24, 12,13,14,15, 16,17,18,19};
__constant__ int c_gstart[5] = {0,5,11,17,21};
__constant__ int c_gn[5]     = {5,6,6,4,4};

__device__ float g_adj[5][6][6];
__device__ float g_H [BT*25*64];
__device__ float g_Z [BT*25*64];
__device__ float g_Y1[BT*25*64];
__device__ float g_Y2[BT*25*128];
__device__ float g_Y3[BT*25*64];
__device__ float g_loss[5*64];
__device__ float g_sb3[5*64];
__device__ float g_cst1[5*64],  g_bb0_1[5*64],  g_bb2_1[5*64];
__device__ float g_cst2[5*128], g_bb0_2[5*128], g_bb2_2[5*128];
__device__ float g_cst3[5*64];
__device__ float g_zero[640];
__device__ float4 g_sw3i[10240];
__device__ float4 g_rw2i[10240];
__device__ float4 g_rw3i[10240];
__device__ float4 g_tw1i[15360];
__device__ float4 g_tw2i[30720];
__device__ float4 g_tw3i[15360];

__device__ __forceinline__ unsigned long long bc2(float x){
    unsigned long long r; unsigned u = __float_as_uint(x);
    asm("mov.b64 %0, {%1, %1};" : "=l"(r) : "r"(u));
    return r;
}
__device__ __forceinline__ unsigned long long pk2(float a, float b){
    unsigned long long r;
    asm("mov.b64 %0, {%1, %2};" : "=l"(r) : "r"(__float_as_uint(a)), "r"(__float_as_uint(b)));
    return r;
}
__device__ __forceinline__ void ffma2(unsigned long long& c, unsigned long long a, unsigned long long b){
    asm("fma.rn.f32x2 %0, %1, %2, %0;" : "+l"(c) : "l"(a), "l"(b));
}
__device__ __forceinline__ void unpk(unsigned long long v, float& lo, float& hi){
    unsigned a,b; asm("mov.b64 {%0, %1}, %2;" : "=r"(a), "=r"(b) : "l"(v));
    lo = __uint_as_float(a); hi = __uint_as_float(b);
}

__global__ __launch_bounds__(256) void k_prep(
    const float* __restrict__ sw1, const float* __restrict__ sb1,
    const float* __restrict__ tw1, const float* __restrict__ tb1,
    const float* __restrict__ rw2, const float* __restrict__ rb2,
    const float* __restrict__ rg2, const float* __restrict__ rbb2,
    const float* __restrict__ sw2, const float* __restrict__ sb2,
    const float* __restrict__ tw2, const float* __restrict__ tb2,
    const float* __restrict__ rw3, const float* __restrict__ rb3,
    const float* __restrict__ rg3, const float* __restrict__ rbb3,
    const float* __restrict__ sw3, const float* __restrict__ sb3,
    const float* __restrict__ tw3, const float* __restrict__ tb3)
{
    int gt  = blockIdx.x*blockDim.x + threadIdx.x;
    int NTH = gridDim.x*blockDim.x;

    for (int e=gt;e<15360;e+=NTH){
        int g=e/3072, r=e%3072, kt=r/1024, r2=r%1024, kk2=r2/32, q=r2%32, jp=q/8, tx=q%8;
        int oa=tx+16*jp, ob=oa+8, k0=2*kk2;
        float v0=0.f,v1=0.f,v2=0.f,v3=0.f;
        for (int c=0;c<64;c++){
            float s0 = sw1[(g*192+c)*64+k0]   + sw1[(g*192+64+c)*64+k0]   + sw1[(g*192+128+c)*64+k0];
            float s1 = sw1[(g*192+c)*64+k0+1] + sw1[(g*192+64+c)*64+k0+1] + sw1[(g*192+128+c)*64+k0+1];
            float wa = tw1[((g*64+oa)*64+c)*3+kt];
            float wb = tw1[((g*64+ob)*64+c)*3+kt];
            v0=fmaf(wa,s0,v0); v1=fmaf(wb,s0,v1); v2=fmaf(wa,s1,v2); v3=fmaf(wb,s1,v3);
        }
        g_tw1i[e]=make_float4(v0,v1,v2,v3);
    }
    for (int e=gt;e<15360;e+=NTH){
        int g=e/3072, r=e%3072, kt=r/1024, r2=r%1024, kk2=r2/32, q=r2%32, jp=q/8, tx=q%8;
        int oa=tx+16*jp, ob=oa+8, k0=2*kk2;
        g_tw3i[e]=make_float4(tw3[((g*64+oa)*64+k0)*3+kt],   tw3[((g*64+ob)*64+k0)*3+kt],
                              tw3[((g*64+oa)*64+k0+1)*3+kt], tw3[((g*64+ob)*64+k0+1)*3+kt]);
    }
    for (int e=gt;e<30720;e+=NTH){
        int g=e/6144, r=e%6144, kt=r/2048, r2=r%2048, kk2=r2/64, q=r2%64, jp=q/16, tx=q%16;
        int oa=tx+32*jp, ob=oa+16, k0=2*kk2;
        float v0=0.f,v1=0.f,v2=0.f,v3=0.f;
        for (int c=0;c<128;c++){
            float s0 = sw2[(g*384+c)*64+k0]   + sw2[(g*384+128+c)*64+k0]   + sw2[(g*384+256+c)*64+k0];
            float s1 = sw2[(g*384+c)*64+k0+1] + sw2[(g*384+128+c)*64+k0+1] + sw2[(g*384+256+c)*64+k0+1];
            float wa = tw2[((g*128+oa)*128+c)*3+kt];
            float wb = tw2[((g*128+ob)*128+c)*3+kt];
            v0=fmaf(wa,s0,v0); v1=fmaf(wb,s0,v1); v2=fmaf(wa,s1,v2); v3=fmaf(wb,s1,v3);
        }
        g_tw2i[e]=make_float4(v0,v1,v2,v3);
    }
    for (int e=gt;e<10240;e+=NTH){
        int g=e/2048, r=e%2048, kk2=r/32, q=r%32, jp=q/8, tx=q%8;
        int oa=tx+16*jp, ob=oa+8, k0=2*kk2;
        const float* w = sw3 + g*192*128;
        #define S3(o,c) (w[(o)*128+(c)] + w[(64+(o))*128+(c)] + w[(128+(o))*128+(c)])
        g_sw3i[e] = make_float4(S3(oa,k0), S3(ob,k0), S3(oa,k0+1), S3(ob,k0+1));
        #undef S3
    }
    for (int e=gt;e<10240;e+=NTH){
        int g=e/2048, r=e%2048, kk2=r/64, q=r%64, jp=q/16, tx=q%16;
        int oa=tx+32*jp, ob=oa+16, k0=2*kk2;
        const float* w = rw2 + g*8192;
        float sa_=rg2[g*128+oa]*BNS, sb_=rg2[g*128+ob]*BNS;
        g_rw2i[e] = make_float4(w[oa*64+k0]*sa_, w[ob*64+k0]*sb_, w[oa*64+k0+1]*sa_, w[ob*64+k0+1]*sb_);
    }
    for (int e=gt;e<10240;e+=NTH){
        int g=e/2048, r=e%2048, kk2=r/32, q=r%32, jp=q/8, tx=q%8;
        int oa=tx+16*jp, ob=oa+8, k0=2*kk2;
        const float* w = rw3 + g*8192;
        float sa_=rg3[g*64+oa]*BNS, sb_=rg3[g*64+ob]*BNS;
        g_rw3i[e] = make_float4(w[oa*128+k0]*sa_, w[ob*128+k0]*sb_, w[oa*128+k0+1]*sa_, w[ob*128+k0+1]*sb_);
    }
    for (int i=gt;i<5*64;i+=NTH){
        int g=i/64, o=i%64;
        float b0=0.f,b1=0.f,b2=0.f;
        for (int c=0;c<64;c++){
            float sb = sb1[g*192+c]+sb1[g*192+64+c]+sb1[g*192+128+c];
            b0=fmaf(tw1[((g*64+o)*64+c)*3+0],sb,b0);
            b1=fmaf(tw1[((g*64+o)*64+c)*3+1],sb,b1);
            b2=fmaf(tw1[((g*64+o)*64+c)*3+2],sb,b2);
        }
        g_cst1[i]=tb1[i]+b0+b1+b2;
        g_bb0_1[i]=b0; g_bb2_1[i]=b2;
        const float* s3=sb3+g*192;
        g_sb3[i]=s3[o]+s3[64+o]+s3[128+o];
        g_cst3[i]=tb3[i]+rb3[i]*rg3[i]*BNS+rbb3[i];
    }
    for (int i=gt;i<5*128;i+=NTH){
        int g=i/128, o=i%128;
        float b0=0.f,b1=0.f,b2=0.f;
        for (int c=0;c<128;c++){
            float sb = sb2[g*384+c]+sb2[g*384+128+c]+sb2[g*384+256+c];
            b0=fmaf(tw2[((g*128+o)*128+c)*3+0],sb,b0);
            b1=fmaf(tw2[((g*128+o)*128+c)*3+1],sb,b1);
            b2=fmaf(tw2[((g*128+o)*128+c)*3+2],sb,b2);
        }
        g_cst2[i]=tb2[i]+rb2[i]*rg2[i]*BNS+rbb2[i]+b0+b1+b2;
        g_bb0_2[i]=b0; g_bb2_2[i]=b2;
    }
    for (int i=gt;i<640;i+=NTH) g_zero[i]=0.f;
    if (gt==0){
        double fa[25][25];
        for (int i=0;i<25;i++) for (int j=0;j<25;j++) fa[i][j]=0.0;
        const int E[24][2]={{3,2},{2,20},{20,1},{1,0},{20,4},{4,5},{5,6},{6,22},
                            {6,7},{7,21},{20,8},{8,9},{9,10},{10,24},{10,11},{11,23},
                            {0,12},{12,13},{13,14},{14,15},{0,16},{16,17},{17,18},{18,19}};
        for (int k=0;k<24;k++){
            int i=E[k][0]-1, j=E[k][1]-1;
            fa[i][j]=1.0; fa[j][i]=1.0;
        }
        for (int i=0;i<25;i++) fa[i][i]+=1.0;
        for (int i=0;i<25;i++){
            double d=0; for (int j=0;j<25;j++) d+=fa[i][j];
            if (d==0.0) d=1.0;
            for (int j=0;j<25;j++) fa[i][j]/=d;
        }
        for (int g=0;g<5;g++){
            int n=c_gn[g];
            int js[6]; for (int u=0;u<n;u++) js[u]=c_s2j[c_gstart[g]+u];
            double sa[6][6];
            for (int u=0;u<n;u++) for (int v=0;v<n;v++) sa[u][v]=fa[js[u]][js[v]];
            for (int u=0;u<n;u++) sa[u][u]+=1.0;
            double dg[6];
            for (int u=0;u<n;u++){ double d=0; for (int v=0;v<n;v++) d+=sa[u][v]; dg[u]=d; }
            for (int node=1;node<n;node++)
                if (dg[node]==1.0){ sa[0][node]=1.0; sa[node][0]=1.0; }
            for (int u=0;u<6;u++) for (int v=0;v<6;v++){
                float val=0.f;
                if (u<n && v<n){
                    double d=0; for (int w=0;w<n;w++) d+=sa[u][w];
                    if (d==0.0) d=1.0;
                    val=(float)(sa[u][v]/d);
                }
                g_adj[g][u][v]=val;
            }
        }
    }
}

__global__ __launch_bounds__(256) void k_embed(const float* __restrict__ x,
                                               const float* __restrict__ ew,
                                               const float* __restrict__ eb)
{
    int idx = blockIdx.x*256 + threadIdx.x;
    int c   = idx & 63;
    int row = idx >> 6;
    int s   = row % 25;
    int bt  = row / 25;
    int j   = c_s2j[s];
    const float* xp = x + (bt*25 + j)*3;
    g_H[idx] = eb[c] + xp[0]*ew[c*3+0] + xp[1]*ew[c*3+1] + xp[2]*ew[c*3+2];
}

template<int CT>
__device__ __forceinline__ void gemm_kk4(unsigned long long (&acc)[6][4],
                                         const float4* aPtr, int aStride,
                                         const ulonglong2* wPtr)
{
    float4 a[6];
    #pragma unroll
    for (int i=0;i<6;++i) a[i] = aPtr[aStride*i];
    #pragma unroll
    for (int h=0;h<2;++h){
        ulonglong2 w0 = wPtr[h*4*CT + 0*CT];
        ulonglong2 w1 = wPtr[h*4*CT + 1*CT];
        ulonglong2 w2 = wPtr[h*4*CT + 2*CT];
        ulonglong2 w3 = wPtr[h*4*CT + 3*CT];
        #pragma unroll
        for (int i=0;i<6;++i){
            unsigned long long alo = bc2(h ? a[i].z : a[i].x);
            unsigned long long ahi = bc2(h ? a[i].w : a[i].y);
            ffma2(acc[i][0], alo, w0.x);
            ffma2(acc[i][1], alo, w1.x);
            ffma2(acc[i][2], alo, w2.x);
            ffma2(acc[i][3], alo, w3.x);
            ffma2(acc[i][0], ahi, w0.y);
            ffma2(acc[i][1], ahi, w1.y);
            ffma2(acc[i][2], ahi, w2.y);
            ffma2(acc[i][3], ahi, w3.y);
        }
    }
}

// Layer-3 GCN: graph conv + 128->64 GEMM (unchanged from R10)
__global__ __launch_bounds__(256) void k_gcn3(const float* __restrict__ Y,
                                              float* __restrict__ Z,
                                              const float4* __restrict__ Wi,
                                              const float* __restrict__ Bv)
{
    constexpr int CT = 8;
    extern __shared__ float sm[];
    float4* sA4 = (float4*)sm;
    float4* sW4 = sA4 + 192*17;
    const ulonglong2* sWl = (const ulonglong2*)sW4;
    __shared__ float sAdj[6][6];

    const int g   = blockIdx.y;
    const int n   = c_gn[g];
    const int gs0 = c_gstart[g];
    const int bt0 = blockIdx.x * 32;
    const int tid = threadIdx.x;
    if (tid < 36) sAdj[tid/6][tid%6] = g_adj[g][tid/6][tid%6];

    const int ty = tid / CT, tx = tid % CT;
    unsigned long long acc[6][4];
    #pragma unroll
    for (int jp=0;jp<4;++jp){
        int oa = tx + 16*jp;
        unsigned long long b2 = pk2(Bv[g*64+oa], Bv[g*64+oa+8]);
        #pragma unroll
        for (int i=0;i<6;++i) acc[i][jp]=b2;
    }
    const float4* Wg = Wi + (size_t)g*2048;

    for (int ph=0; ph<2; ++ph){
        __syncthreads();
        for (int p=tid; p<192*16; p+=256){
            int c4l = p % 16, r = p / 16, u = r % 6, t = r / 6;
            int c4 = ph*16 + c4l;
            float4 v = make_float4(0.f,0.f,0.f,0.f);
            if (u < n){
                const float4* yp = (const float4*)(Y + ((size_t)(bt0+t)*25 + gs0)*128) + c4;
                #pragma unroll
                for (int vv=0; vv<6; ++vv)
                    if (vv < n){
                        float av = sAdj[u][vv];
                        float4 yv = yp[(size_t)vv*32];
                        v.x += av*yv.x; v.y += av*yv.y; v.z += av*yv.z; v.w += av*yv.w;
                    }
            }
            sA4[r*17 + c4l] = v;
        }
        for (int p=tid; p<1024; p+=256) sW4[p] = Wg[ph*1024 + p];
        __syncthreads();
        #pragma unroll 8
        for (int kk4l=0;kk4l<16;++kk4l)
            gemm_kk4<CT>(acc, sA4 + ty*17 + kk4l, 32*17, sWl + 2*kk4l*4*CT + tx);
    }

    #pragma unroll
    for (int i=0;i<6;++i){
        int r = ty+32*i, t = r/6, u = r%6;
        if (u < n){
            float* zp = Z + ((size_t)(bt0+t)*25 + gs0+u)*64;
            #pragma unroll
            for (int jp=0;jp<4;++jp){
                float lo,hi; unpk(acc[i][jp], lo, hi);
                int oa = tx + 16*jp;
                zp[oa] = lo; zp[oa+8] = hi;
            }
        }
    }
}

// tconv with temporal A-reuse: thread = (u, tt, tx); 8 consecutive timesteps x 8 cols.
// All 3 taps resident (k-halved for NP=2). CIN=64.
template<int COUT,int CRES,int MODE,int GCONV,int TT,int NP>
__global__ __launch_bounds__(6*TT*(COUT/8))
void k_tconv(const float* __restrict__ Zin, const float* __restrict__ Yres,
             float* __restrict__ Yout,
             const float4* __restrict__ TWi, const float4* __restrict__ RWi,
             const float* __restrict__ CST, const float* __restrict__ BB0,
             const float* __restrict__ BB2,
             const float* __restrict__ GS, const float* __restrict__ BB)
{
    constexpr int CT    = COUT/8;
    constexpr int TH    = 6*TT*CT;
    constexpr int TBL   = 8*TT;
    constexpr int C4    = 16;
    constexpr int PRZ   = 17;
    constexpr int KK2PP = 32/NP;
    constexpr int KST   = KK2PP*4*CT;   // smem f4 per kt per pass
    constexpr int PERKT = 32*4*CT;      // global f4 per kt
    constexpr int WENT  = 3*KST;
    constexpr int SBUF4 = (TBL+2)*6*PRZ;
    extern __shared__ float sm[];
    float4* sB4 = (float4*)sm;
    float4* sW4 = sB4 + SBUF4;
    const ulonglong2* sWl = (const ulonglong2*)sW4;
    __shared__ float sAdj[6][6];

    const int g   = blockIdx.y;
    const int n   = c_gn[g];
    const int gs0 = c_gstart[g];
    const int bt0 = blockIdx.x * TBL;
    const int t0  = bt0 & (NT-1);
    const int tid = threadIdx.x;
    const int tx  = tid % CT;
    const int tt  = (tid / CT) % TT;
    const int u   = tid / (CT*TT);

    if (GCONV){
        if (tid < 36) sAdj[tid/6][tid%6] = g_adj[g][tid/6][tid%6];
        __syncthreads();
    }

    // stage A window (halo) with optional fused graph conv
    for (int p=tid; p<(TBL+2)*6*C4; p+=TH){
        int c4 = p % C4, r = p / C4, uu = r % 6, hb = r / 6;
        int t = t0 + hb - 1;
        float4 v = make_float4(0.f,0.f,0.f,0.f);
        if (t >= 0 && t < NT){
            if (GCONV){
                const float4* yp = (const float4*)(Zin + ((size_t)(bt0+hb-1)*25 + gs0)*64) + c4;
                #pragma unroll
                for (int vv=0; vv<6; ++vv)
                    if (vv < n){
                        float av = sAdj[uu][vv];
                        float4 yv = yp[(size_t)vv*C4];
                        v.x += av*yv.x; v.y += av*yv.y; v.z += av*yv.z; v.w += av*yv.w;
                    }
            } else if (uu < n){
                v = ((const float4*)(Zin + ((size_t)(bt0+hb-1)*25 + gs0+uu)*64))[c4];
            }
        }
        sB4[r*PRZ + c4] = v;
    }

    unsigned long long acc[8][4];
    unsigned long long z2 = pk2(0.f,0.f);
    #pragma unroll
    for (int m=0;m<8;++m)
        #pragma unroll
        for (int jp=0;jp<4;++jp) acc[m][jp]=z2;

    const float4* TWg = TWi + (size_t)g*3*PERKT;
    for (int ph=0; ph<NP; ++ph){
        __syncthreads();
        for (int p=tid; p<WENT; p+=TH){
            int kt = p / KST, rem = p % KST;
            sW4[p] = TWg[kt*PERKT + ph*KST + rem];
        }
        __syncthreads();
        #pragma unroll 1
        for (int kk4l=0; kk4l<KK2PP/2; ++kk4l){
            int c4 = ph*(KK2PP/2) + kk4l;
            float4 a[10];
            #pragma unroll
            for (int j=0;j<10;++j)
                a[j] = sB4[((tt*8+j)*6 + u)*PRZ + c4];
            #pragma unroll
            for (int kt=0;kt<3;++kt){
                const ulonglong2* wb = sWl + kt*KST + 2*kk4l*4*CT + tx;
                #pragma unroll
                for (int h=0;h<2;++h){
                    ulonglong2 w0=wb[h*4*CT], w1=wb[h*4*CT+CT], w2=wb[h*4*CT+2*CT], w3=wb[h*4*CT+3*CT];
                    #pragma unroll
                    for (int m=0;m<8;++m){
                        float4 av = a[m+kt];
                        unsigned long long alo = bc2(h ? av.z : av.x);
                        unsigned long long ahi = bc2(h ? av.w : av.y);
                        ffma2(acc[m][0], alo, w0.x);
                        ffma2(acc[m][1], alo, w1.x);
                        ffma2(acc[m][2], alo, w2.x);
                        ffma2(acc[m][3], alo, w3.x);
                        ffma2(acc[m][0], ahi, w0.y);
                        ffma2(acc[m][1], ahi, w1.y);
                        ffma2(acc[m][2], ahi, w2.y);
                        ffma2(acc[m][3], ahi, w3.y);
                    }
                }
            }
        }
    }

    if (MODE==1){
        constexpr int RPASS = CRES/64;
        constexpr int RWP   = 32*4*CT;
        const float4* RWg = RWi + (size_t)g*(RPASS*RWP);
        for (int ph=0; ph<RPASS; ++ph){
            __syncthreads();
            for (int p=tid; p<TBL*6*16; p+=TH){
                int c4l = p % 16, r = p / 16, uu = r % 6, t = r / 6;
                float4 v = make_float4(0.f,0.f,0.f,0.f);
                if (uu < n)
                    v = ((const float4*)(Yres + ((size_t)(bt0+t)*25 + gs0+uu)*CRES))[ph*16 + c4l];
                sB4[r*PRZ + c4l] = v;
            }
            for (int p=tid; p<RWP; p+=TH) sW4[p] = RWg[ph*RWP + p];
            __syncthreads();
            #pragma unroll 1
            for (int kk4l=0; kk4l<16; ++kk4l){
                float4 a2[8];
                #pragma unroll
                for (int m=0;m<8;++m)
                    a2[m] = sB4[((tt*8+m)*6 + u)*PRZ + kk4l];
                const ulonglong2* wb = sWl + 2*kk4l*4*CT + tx;
                #pragma unroll
                for (int h=0;h<2;++h){
                    ulonglong2 w0=wb[h*4*CT], w1=wb[h*4*CT+CT], w2=wb[h*4*CT+2*CT], w3=wb[h*4*CT+3*CT];
                    #pragma unroll
                    for (int m=0;m<8;++m){
                        float4 av = a2[m];
                        unsigned long long alo = bc2(h ? av.z : av.x);
                        unsigned long long ahi = bc2(h ? av.w : av.y);
                        ffma2(acc[m][0], alo, w0.x);
                        ffma2(acc[m][1], alo, w1.x);
                        ffma2(acc[m][2], alo, w2.x);
                        ffma2(acc[m][3], alo, w3.x);
                        ffma2(acc[m][0], ahi, w0.y);
                        ffma2(acc[m][1], ahi, w1.y);
                        ffma2(acc[m][2], ahi, w2.y);
                        ffma2(acc[m][3], ahi, w3.y);
                    }
                }
            }
        }
    }

    float cst[8], gsv[8], bbv[8];
    #pragma unroll
    for (int jp=0;jp<4;++jp){
        int oa = tx + CT*2*jp;
        cst[2*jp]   = CST[g*COUT+oa];       cst[2*jp+1] = CST[g*COUT+oa+CT];
        gsv[2*jp]   = GS [g*COUT+oa]*BNS;   gsv[2*jp+1] = GS [g*COUT+oa+CT]*BNS;
        bbv[2*jp]   = BB [g*COUT+oa];       bbv[2*jp+1] = BB [g*COUT+oa+CT];
    }
    if (u < n){
        #pragma unroll
        for (int m=0;m<8;++m){
            int t_loc = tt*8 + m;
            size_t base = ((size_t)(bt0+t_loc)*25 + gs0+u)*COUT;
            int tg = t0 + t_loc;
            bool e0 = (tg==0), e2 = (tg==NT-1);
            #pragma unroll
            for (int jp=0;jp<4;++jp){
                float lo,hi; unpk(acc[m][jp], lo, hi);
                int oa = tx + CT*2*jp;
                float pa = lo + cst[2*jp];
                float pb = hi + cst[2*jp+1];
                if (e0){ pa -= BB0[g*COUT+oa]; pb -= BB0[g*COUT+oa+CT]; }
                if (e2){ pa -= BB2[g*COUT+oa]; pb -= BB2[g*COUT+oa+CT]; }
                if (MODE==0){ pa += Yres[base+oa]; pb += Yres[base+oa+CT]; }
                Yout[base+oa]    = fmaxf(pa*gsv[2*jp]   + bbv[2*jp],   0.f);
                Yout[base+oa+CT] = fmaxf(pb*gsv[2*jp+1] + bbv[2*jp+1], 0.f);
            }
        }
    }
}

__global__ __launch_bounds__(256) void k_featvq(const float* __restrict__ cb,
                                                float* __restrict__ out)
{
    int g = blockIdx.x, b = blockIdx.y;
    int tid = threadIdx.x;
    int o = tid & 63, part = tid >> 6;
    int n = c_gn[g], gs0 = c_gstart[g];
    float s = 0.f;
    int total = NT*n;
    for (int q=part; q<total; q+=4){
        int t = q / n, u = q % n;
        s += g_Y3[((size_t)(b*NT+t)*25 + gs0+u)*64 + o];
    }
    __shared__ float red[256];
    __shared__ float f[64];
    red[tid]=s; __syncthreads();
    if (part==0)
        f[o] = (red[o]+red[64+o]+red[128+o]+red[192+o]) / (float)(NT*n);
    __syncthreads();

    __shared__ float ds[128];
    __shared__ int   sidx;
    if (tid < 128){
        const float* ck = cb + (g*128 + tid)*64;
        float dot=0.f, scb=0.f;
        for (int oo=0;oo<64;++oo){ dot += f[oo]*ck[oo]; scb += ck[oo]*ck[oo]; }
        ds[tid] = scb - 2.f*dot;
    }
    __syncthreads();
    if (tid==0){
        float best = ds[0]; int bi = 0;
        for (int kk=1;kk<128;++kk) if (ds[kk] < best){ best = ds[kk]; bi = kk; }
        sidx = bi;
    }
    __syncthreads();
    int idx = sidx;
    __shared__ float dsq[64];
    if (tid < 64){
        float q = cb[(g*128 + idx)*64 + tid];
        out[(g*64+b)*64 + tid] = q;
        float dd = q - f[tid];
        dsq[tid] = dd*dd;
    }
    __syncthreads();
    if (tid==0){
        float ss=0.f;
        for (int oo=0;oo<64;++oo) ss += dsq[oo];
        g_loss[g*64+b] = 1.25f * ss / 4096.f;
        out[5*64*64 + 1 + g*64 + b] = (float)idx;
    }
}

__global__ void k_lred(float* out){
    __shared__ float s[320];
    int t = threadIdx.x;
    if (t < 320) s[t] = g_loss[t];
    __syncthreads();
    if (t==0){
        float a=0.f;
        for (int i=0;i<320;i++) a += s[i];
        out[5*64*64] = a;
    }
}

extern "C" void kernel_launch(void* const* d_in, const int* in_sizes, int n_in,
                              void* d_out, int out_size)
{
    const float* x        = (const float*)d_in[0];
    const float* embed_w  = (const float*)d_in[1];
    const float* embed_b  = (const float*)d_in[2];
    const float* sgcn_w1  = (const float*)d_in[3];
    const float* sgcn_b1  = (const float*)d_in[4];
    const float* tconv_w1 = (const float*)d_in[5];
    const float* tconv_b1 = (const float*)d_in[6];
    const float* bn_g1    = (const float*)d_in[7];
    const float* bn_b1    = (const float*)d_in[8];
    const float* res_w2   = (const float*)d_in[9];
    const float* res_b2   = (const float*)d_in[10];
    const float* resbn_g2 = (const float*)d_in[11];
    const float* resbn_b2 = (const float*)d_in[12];
    const float* sgcn_w2  = (const float*)d_in[13];
    const float* sgcn_b2  = (const float*)d_in[14];
    const float* tconv_w2 = (const float*)d_in[15];
    const float* tconv_b2 = (const float*)d_in[16];
    const float* bn_g2    = (const float*)d_in[17];
    const float* bn_b2    = (const float*)d_in[18];
    const float* res_w3   = (const float*)d_in[19];
    const float* res_b3   = (const float*)d_in[20];
    const float* resbn_g3 = (const float*)d_in[21];
    const float* resbn_b3 = (const float*)d_in[22];
    const float* sgcn_w3  = (const float*)d_in[23];
    const float* sgcn_b3  = (const float*)d_in[24];
    const float* tconv_w3 = (const float*)d_in[25];
    const float* tconv_b3 = (const float*)d_in[26];
    const float* bn_g3    = (const float*)d_in[27];
    const float* bn_b3    = (const float*)d_in[28];
    const float* codebooks= (const float*)d_in[29];
    float* out = (float*)d_out;

    void *vp;
    #define SYM(name, s, T) cudaGetSymbolAddress(&vp, s); T* name = (T*)vp;
    SYM(pH,  g_H,  float)  SYM(pZ, g_Z, float)  SYM(pY1, g_Y1, float)
    SYM(pY2, g_Y2, float)  SYM(pY3, g_Y3, float)
    SYM(pSB3,g_sb3,float)
    SYM(pC1, g_cst1,float) SYM(pB01,g_bb0_1,float) SYM(pB21,g_bb2_1,float)
    SYM(pC2, g_cst2,float) SYM(pB02,g_bb0_2,float) SYM(pB22,g_bb2_2,float)
    SYM(pC3, g_cst3,float) SYM(pZERO,g_zero,float)
    SYM(pSW3,g_sw3i,float4)
    SYM(pRW2,g_rw2i,float4) SYM(pRW3,g_rw3i,float4)
    SYM(pTW1,g_tw1i,float4) SYM(pTW2,g_tw2i,float4) SYM(pTW3,g_tw3i,float4)
    #undef SYM

    dim3 grid16(BT/16, 5);   // tconv2 (TBL=16)
    dim3 grid32(BT/32, 5);   // tconv1/3 (TBL=32), gcn3

    size_t sm_t1 = (34*6*17 + 3*1024)*16;   // 104.6 KB
    size_t sm_t2 = (18*6*17 + 3*1024)*16;   // 78.5 KB
    size_t sm_t3 = sm_t1;
    size_t sm_g3 = (192*17 + 1024)*16;      // 68.6 KB

    cudaFuncSetAttribute((k_tconv<64,64,0,1,4,1>),   cudaFuncAttributeMaxDynamicSharedMemorySize, (int)sm_t1);
    cudaFuncSetAttribute((k_tconv<128,64,1,1,2,2>),  cudaFuncAttributeMaxDynamicSharedMemorySize, (int)sm_t2);
    cudaFuncSetAttribute(k_gcn3,                     cudaFuncAttributeMaxDynamicSharedMemorySize, (int)sm_g3);
    cudaFuncSetAttribute((k_tconv<64,128,1,0,4,1>),  cudaFuncAttributeMaxDynamicSharedMemorySize, (int)sm_t3);

    k_prep<<<64,256>>>(sgcn_w1, sgcn_b1, tconv_w1, tconv_b1,
                       res_w2, res_b2, resbn_g2, resbn_b2, sgcn_w2, sgcn_b2, tconv_w2, tconv_b2,
                       res_w3, res_b3, resbn_g3, resbn_b3, sgcn_w3, sgcn_b3, tconv_w3, tconv_b3);

    k_embed<<<BT*25*64/256, 256>>>(x, embed_w, embed_b);

    k_tconv<64,64,0,1,4,1><<<grid32,192,sm_t1>>>(pH, pH, pY1, pTW1, pRW2,
                                                 pC1, pB01, pB21, bn_g1, bn_b1);
    k_tconv<128,64,1,1,2,2><<<grid16,192,sm_t2>>>(pY1, pY1, pY2, pTW2, pRW2,
                                                  pC2, pB02, pB22, bn_g2, bn_b2);
    k_gcn3<<<grid32,256,sm_g3>>>(pY2, pZ, pSW3, pSB3);
    k_tconv<64,128,1,0,4,1><<<grid32,192,sm_t3>>>(pZ, pY2, pY3, pTW3, pRW3,
                                                  pC3, pZERO, pZERO, bn_g3, bn_b3);

    k_featvq<<<dim3(5,64),256>>>(codebooks, out);
    k_lred<<<1,512>>>(out);
}

// round 12
// speedup vs baseline: 1.1355x; 1.1355x over previous
#include <cuda_runtime.h>

#define NB 64
#define NT 256
#define BT (NB*NT)
#define BNS 0.9999950000374997f

__constant__ int c_s2j[25] = {0,1,2,3,20, 4,5,6,7,21,22, 8,9,10,11,23,24, 12,13,14,15, 16,17,18,19};
__constant__ int c_gstart[5] = {0,5,11,17,21};
__constant__ int c_gn[5]     = {5,6,6,4,4};

__device__ float g_adj[5][6][6];
__device__ float g_Z [BT*25*64];
__device__ float g_Y1[BT*25*64];
__device__ float g_Y2[BT*25*128];
__device__ float g_Y3[BT*25*64];
__device__ float g_loss[5*64];
__device__ float g_sb3[5*64];
__device__ float g_cst1[5*64],  g_bb0_1[5*64],  g_bb2_1[5*64];
__device__ float g_cst2[5*128], g_bb0_2[5*128], g_bb2_2[5*128];
__device__ float g_cst3[5*64];
__device__ float g_zero[640];
__device__ float4 g_sw3i[10240];
__device__ float4 g_rw2i[10240];
__device__ float4 g_rw3i[10240];
__device__ float4 g_tw1i[15360];
__device__ float4 g_tw2i[30720];
__device__ float4 g_tw3i[15360];

__device__ __forceinline__ unsigned long long bc2(float x){
    unsigned long long r; unsigned u = __float_as_uint(x);
    asm("mov.b64 %0, {%1, %1};" : "=l"(r) : "r"(u));
    return r;
}
__device__ __forceinline__ unsigned long long pk2(float a, float b){
    unsigned long long r;
    asm("mov.b64 %0, {%1, %2};" : "=l"(r) : "r"(__float_as_uint(a)), "r"(__float_as_uint(b)));
    return r;
}
__device__ __forceinline__ void ffma2(unsigned long long& c, unsigned long long a, unsigned long long b){
    asm("fma.rn.f32x2 %0, %1, %2, %0;" : "+l"(c) : "l"(a), "l"(b));
}
__device__ __forceinline__ void unpk(unsigned long long v, float& lo, float& hi){
    unsigned a,b; asm("mov.b64 {%0, %1}, %2;" : "=r"(a), "=r"(b) : "l"(v));
    lo = __uint_as_float(a); hi = __uint_as_float(b);
}

__global__ __launch_bounds__(256) void k_prep(
    const float* __restrict__ sw1, const float* __restrict__ sb1,
    const float* __restrict__ tw1, const float* __restrict__ tb1,
    const float* __restrict__ rw2, const float* __restrict__ rb2,
    const float* __restrict__ rg2, const float* __restrict__ rbb2,
    const float* __restrict__ sw2, const float* __restrict__ sb2,
    const float* __restrict__ tw2, const float* __restrict__ tb2,
    const float* __restrict__ rw3, const float* __restrict__ rb3,
    const float* __restrict__ rg3, const float* __restrict__ rbb3,
    const float* __restrict__ sw3, const float* __restrict__ sb3,
    const float* __restrict__ tw3, const float* __restrict__ tb3)
{
    int gt  = blockIdx.x*blockDim.x + threadIdx.x;
    int NTH = gridDim.x*blockDim.x;

    for (int e=gt;e<15360;e+=NTH){
        int g=e/3072, r=e%3072, kt=r/1024, r2=r%1024, kk2=r2/32, q=r2%32, jp=q/8, tx=q%8;
        int oa=tx+16*jp, ob=oa+8, k0=2*kk2;
        float v0=0.f,v1=0.f,v2=0.f,v3=0.f;
        for (int c=0;c<64;c++){
            float s0 = sw1[(g*192+c)*64+k0]   + sw1[(g*192+64+c)*64+k0]   + sw1[(g*192+128+c)*64+k0];
            float s1 = sw1[(g*192+c)*64+k0+1] + sw1[(g*192+64+c)*64+k0+1] + sw1[(g*192+128+c)*64+k0+1];
            float wa = tw1[((g*64+oa)*64+c)*3+kt];
            float wb = tw1[((g*64+ob)*64+c)*3+kt];
            v0=fmaf(wa,s0,v0); v1=fmaf(wb,s0,v1); v2=fmaf(wa,s1,v2); v3=fmaf(wb,s1,v3);
        }
        g_tw1i[e]=make_float4(v0,v1,v2,v3);
    }
    for (int e=gt;e<15360;e+=NTH){
        int g=e/3072, r=e%3072, kt=r/1024, r2=r%1024, kk2=r2/32, q=r2%32, jp=q/8, tx=q%8;
        int oa=tx+16*jp, ob=oa+8, k0=2*kk2;
        g_tw3i[e]=make_float4(tw3[((g*64+oa)*64+k0)*3+kt],   tw3[((g*64+ob)*64+k0)*3+kt],
                              tw3[((g*64+oa)*64+k0+1)*3+kt], tw3[((g*64+ob)*64+k0+1)*3+kt]);
    }
    for (int e=gt;e<30720;e+=NTH){
        int g=e/6144, r=e%6144, kt=r/2048, r2=r%2048, kk2=r2/64, q=r2%64, jp=q/16, tx=q%16;
        int oa=tx+32*jp, ob=oa+16, k0=2*kk2;
        float v0=0.f,v1=0.f,v2=0.f,v3=0.f;
        for (int c=0;c<128;c++){
            float s0 = sw2[(g*384+c)*64+k0]   + sw2[(g*384+128+c)*64+k0]   + sw2[(g*384+256+c)*64+k0];
            float s1 = sw2[(g*384+c)*64+k0+1] + sw2[(g*384+128+c)*64+k0+1] + sw2[(g*384+256+c)*64+k0+1];
            float wa = tw2[((g*128+oa)*128+c)*3+kt];
            float wb = tw2[((g*128+ob)*128+c)*3+kt];
            v0=fmaf(wa,s0,v0); v1=fmaf(wb,s0,v1); v2=fmaf(wa,s1,v2); v3=fmaf(wb,s1,v3);
        }
        g_tw2i[e]=make_float4(v0,v1,v2,v3);
    }
    for (int e=gt;e<10240;e+=NTH){
        int g=e/2048, r=e%2048, kk2=r/32, q=r%32, jp=q/8, tx=q%8;
        int oa=tx+16*jp, ob=oa+8, k0=2*kk2;
        const float* w = sw3 + g*192*128;
        #define S3(o,c) (w[(o)*128+(c)] + w[(64+(o))*128+(c)] + w[(128+(o))*128+(c)])
        g_sw3i[e] = make_float4(S3(oa,k0), S3(ob,k0), S3(oa,k0+1), S3(ob,k0+1));
        #undef S3
    }
    for (int e=gt;e<10240;e+=NTH){
        int g=e/2048, r=e%2048, kk2=r/64, q=r%64, jp=q/16, tx=q%16;
        int oa=tx+32*jp, ob=oa+16, k0=2*kk2;
        const float* w = rw2 + g*8192;
        float sa_=rg2[g*128+oa]*BNS, sb_=rg2[g*128+ob]*BNS;
        g_rw2i[e] = make_float4(w[oa*64+k0]*sa_, w[ob*64+k0]*sb_, w[oa*64+k0+1]*sa_, w[ob*64+k0+1]*sb_);
    }
    for (int e=gt;e<10240;e+=NTH){
        int g=e/2048, r=e%2048, kk2=r/32, q=r%32, jp=q/8, tx=q%8;
        int oa=tx+16*jp, ob=oa+8, k0=2*kk2;
        const float* w = rw3 + g*8192;
        float sa_=rg3[g*64+oa]*BNS, sb_=rg3[g*64+ob]*BNS;
        g_rw3i[e] = make_float4(w[oa*128+k0]*sa_, w[ob*128+k0]*sb_, w[oa*128+k0+1]*sa_, w[ob*128+k0+1]*sb_);
    }
    for (int i=gt;i<5*64;i+=NTH){
        int g=i/64, o=i%64;
        float b0=0.f,b1=0.f,b2=0.f;
        for (int c=0;c<64;c++){
            float sb = sb1[g*192+c]+sb1[g*192+64+c]+sb1[g*192+128+c];
            b0=fmaf(tw1[((g*64+o)*64+c)*3+0],sb,b0);
            b1=fmaf(tw1[((g*64+o)*64+c)*3+1],sb,b1);
            b2=fmaf(tw1[((g*64+o)*64+c)*3+2],sb,b2);
        }
        g_cst1[i]=tb1[i]+b0+b1+b2;
        g_bb0_1[i]=b0; g_bb2_1[i]=b2;
        const float* s3=sb3+g*192;
        g_sb3[i]=s3[o]+s3[64+o]+s3[128+o];
        g_cst3[i]=tb3[i]+rb3[i]*rg3[i]*BNS+rbb3[i];
    }
    for (int i=gt;i<5*128;i+=NTH){
        int g=i/128, o=i%128;
        float b0=0.f,b1=0.f,b2=0.f;
        for (int c=0;c<128;c++){
            float sb = sb2[g*384+c]+sb2[g*384+128+c]+sb2[g*384+256+c];
            b0=fmaf(tw2[((g*128+o)*128+c)*3+0],sb,b0);
            b1=fmaf(tw2[((g*128+o)*128+c)*3+1],sb,b1);
            b2=fmaf(tw2[((g*128+o)*128+c)*3+2],sb,b2);
        }
        g_cst2[i]=tb2[i]+rb2[i]*rg2[i]*BNS+rbb2[i]+b0+b1+b2;
        g_bb0_2[i]=b0; g_bb2_2[i]=b2;
    }
    for (int i=gt;i<640;i+=NTH) g_zero[i]=0.f;
    if (gt==0){
        double fa[25][25];
        for (int i=0;i<25;i++) for (int j=0;j<25;j++) fa[i][j]=0.0;
        const int E[24][2]={{3,2},{2,20},{20,1},{1,0},{20,4},{4,5},{5,6},{6,22},
                            {6,7},{7,21},{20,8},{8,9},{9,10},{10,24},{10,11},{11,23},
                            {0,12},{12,13},{13,14},{14,15},{0,16},{16,17},{17,18},{18,19}};
        for (int k=0;k<24;k++){
            int i=E[k][0]-1, j=E[k][1]-1;
            fa[i][j]=1.0; fa[j][i]=1.0;
        }
        for (int i=0;i<25;i++) fa[i][i]+=1.0;
        for (int i=0;i<25;i++){
            double d=0; for (int j=0;j<25;j++) d+=fa[i][j];
            if (d==0.0) d=1.0;
            for (int j=0;j<25;j++) fa[i][j]/=d;
        }
        for (int g=0;g<5;g++){
            int n=c_gn[g];
            int js[6]; for (int u=0;u<n;u++) js[u]=c_s2j[c_gstart[g]+u];
            double sa[6][6];
            for (int u=0;u<n;u++) for (int v=0;v<n;v++) sa[u][v]=fa[js[u]][js[v]];
            for (int u=0;u<n;u++) sa[u][u]+=1.0;
            double dg[6];
            for (int u=0;u<n;u++){ double d=0; for (int v=0;v<n;v++) d+=sa[u][v]; dg[u]=d; }
            for (int node=1;node<n;node++)
                if (dg[node]==1.0){ sa[0][node]=1.0; sa[node][0]=1.0; }
            for (int u=0;u<6;u++) for (int v=0;v<6;v++){
                float val=0.f;
                if (u<n && v<n){
                    double d=0; for (int w=0;w<n;w++) d+=sa[u][w];
                    if (d==0.0) d=1.0;
                    val=(float)(sa[u][v]/d);
                }
                g_adj[g][u][v]=val;
            }
        }
    }
}

template<int CT>
__device__ __forceinline__ void gemm_kk4(unsigned long long (&acc)[6][4],
                                         const float4* aPtr, int aStride,
                                         const ulonglong2* wPtr)
{
    float4 a[6];
    #pragma unroll
    for (int i=0;i<6;++i) a[i] = aPtr[aStride*i];
    #pragma unroll
    for (int h=0;h<2;++h){
        ulonglong2 w0 = wPtr[h*4*CT + 0*CT];
        ulonglong2 w1 = wPtr[h*4*CT + 1*CT];
        ulonglong2 w2 = wPtr[h*4*CT + 2*CT];
        ulonglong2 w3 = wPtr[h*4*CT + 3*CT];
        #pragma unroll
        for (int i=0;i<6;++i){
            unsigned long long alo = bc2(h ? a[i].z : a[i].x);
            unsigned long long ahi = bc2(h ? a[i].w : a[i].y);
            ffma2(acc[i][0], alo, w0.x);
            ffma2(acc[i][1], alo, w1.x);
            ffma2(acc[i][2], alo, w2.x);
            ffma2(acc[i][3], alo, w3.x);
            ffma2(acc[i][0], ahi, w0.y);
            ffma2(acc[i][1], ahi, w1.y);
            ffma2(acc[i][2], ahi, w2.y);
            ffma2(acc[i][3], ahi, w3.y);
        }
    }
}

// Layer-3 GCN (unchanged from R10)
__global__ __launch_bounds__(256) void k_gcn3(const float* __restrict__ Y,
                                              float* __restrict__ Z,
                                              const float4* __restrict__ Wi,
                                              const float* __restrict__ Bv)
{
    constexpr int CT = 8;
    extern __shared__ float sm[];
    float4* sA4 = (float4*)sm;
    float4* sW4 = sA4 + 192*17;
    const ulonglong2* sWl = (const ulonglong2*)sW4;
    __shared__ float sAdj[6][6];

    const int g   = blockIdx.y;
    const int n   = c_gn[g];
    const int gs0 = c_gstart[g];
    const int bt0 = blockIdx.x * 32;
    const int tid = threadIdx.x;
    if (tid < 36) sAdj[tid/6][tid%6] = g_adj[g][tid/6][tid%6];

    const int ty = tid / CT, tx = tid % CT;
    unsigned long long acc[6][4];
    #pragma unroll
    for (int jp=0;jp<4;++jp){
        int oa = tx + 16*jp;
        unsigned long long b2 = pk2(Bv[g*64+oa], Bv[g*64+oa+8]);
        #pragma unroll
        for (int i=0;i<6;++i) acc[i][jp]=b2;
    }
    const float4* Wg = Wi + (size_t)g*2048;

    for (int ph=0; ph<2; ++ph){
        __syncthreads();
        for (int p=tid; p<192*16; p+=256){
            int c4l = p % 16, r = p / 16, u = r % 6, t = r / 6;
            int c4 = ph*16 + c4l;
            float4 v = make_float4(0.f,0.f,0.f,0.f);
            if (u < n){
                const float4* yp = (const float4*)(Y + ((size_t)(bt0+t)*25 + gs0)*128) + c4;
                #pragma unroll
                for (int vv=0; vv<6; ++vv)
                    if (vv < n){
                        float av = sAdj[u][vv];
                        float4 yv = yp[(size_t)vv*32];
                        v.x += av*yv.x; v.y += av*yv.y; v.z += av*yv.z; v.w += av*yv.w;
                    }
            }
            sA4[r*17 + c4l] = v;
        }
        for (int p=tid; p<1024; p+=256) sW4[p] = Wg[ph*1024 + p];
        __syncthreads();
        #pragma unroll 8
        for (int kk4l=0;kk4l<16;++kk4l)
            gemm_kk4<CT>(acc, sA4 + ty*17 + kk4l, 32*17, sWl + 2*kk4l*4*CT + tx);
    }

    #pragma unroll
    for (int i=0;i<6;++i){
        int r = ty+32*i, t = r/6, u = r%6;
        if (u < n){
            float* zp = Z + ((size_t)(bt0+t)*25 + gs0+u)*64;
            #pragma unroll
            for (int jp=0;jp<4;++jp){
                float lo,hi; unpk(acc[i][jp], lo, hi);
                int oa = tx + 16*jp;
                zp[oa] = lo; zp[oa+8] = hi;
            }
        }
    }
}

// tconv: TBL=16, per-kt W staging, optional fused graph conv; EMB=1 computes the
// embed layer (H = x@ew+eb) on the fly from a tiny staged x tile.
template<int COUT,int CRES,int MODE,int GCONV,int EMB>
__global__ __launch_bounds__((COUT/8)*16)
void k_tconv(const float* __restrict__ Zin, const float* __restrict__ Yres,
             float* __restrict__ Yout,
             const float4* __restrict__ TWi, const float4* __restrict__ RWi,
             const float* __restrict__ CST, const float* __restrict__ BB0,
             const float* __restrict__ BB2,
             const float* __restrict__ GS, const float* __restrict__ BB,
             const float* __restrict__ EW, const float* __restrict__ EB)
{
    constexpr int CT  = COUT/8;
    constexpr int TH  = CT*16;
    constexpr int C4  = 16;
    constexpr int PRZ = 17;
    constexpr int TBL = 16;
    constexpr int WKT = 32*4*CT;
    constexpr int SBUF4 = (TBL+2)*6*PRZ;    // 1836
    extern __shared__ float sm[];
    float4* sB4 = (float4*)sm;
    float4* sW4 = sB4 + SBUF4;
    const ulonglong2* sWl = (const ulonglong2*)sW4;
    float* sX  = (float*)(sW4 + WKT);       // [18*6*3] (EMB only)
    float* sEW = sX + 18*6*3;               // [192]
    float* sEB = sEW + 192;                 // [64]
    __shared__ float sAdj[6][6];

    const int g   = blockIdx.y;
    const int n   = c_gn[g];
    const int gs0 = c_gstart[g];
    const int bt0 = blockIdx.x * TBL;
    const int t0  = bt0 & (NT-1);
    const int tid = threadIdx.x, ty = tid/CT, tx = tid%CT;

    if (GCONV){
        if (tid < 36) sAdj[tid/6][tid%6] = g_adj[g][tid/6][tid%6];
    }
    if (EMB){
        for (int p=tid; p<192; p+=TH) sEW[p] = EW[p];
        for (int p=tid; p<64;  p+=TH) sEB[p] = EB[p];
        for (int p=tid; p<18*6; p+=TH){
            int u = p % 6, hb = p / 6;
            int t = t0 + hb - 1;
            float x0=0.f,x1=0.f,x2=0.f;
            if (t >= 0 && t < NT && u < n){
                int j = c_s2j[gs0+u];
                const float* xp = Zin + ((size_t)(bt0+hb-1)*25 + j)*3;
                x0=xp[0]; x1=xp[1]; x2=xp[2];
            }
            sX[p*3+0]=x0; sX[p*3+1]=x1; sX[p*3+2]=x2;
        }
    }
    if (GCONV || EMB) __syncthreads();

    // stage A window (halo), graph conv fused; EMB computes H from sX on the fly
    for (int p=tid; p<(TBL+2)*6*C4; p+=TH){
        int c4 = p % C4, r = p / C4, uu = r % 6, hb = r / 6;
        int t = t0 + hb - 1;
        float4 v = make_float4(0.f,0.f,0.f,0.f);
        if (t >= 0 && t < NT){
            if (EMB){
                #pragma unroll
                for (int vv=0; vv<6; ++vv)
                    if (vv < n){
                        float av = sAdj[uu][vv];
                        const float* xr = sX + (hb*6+vv)*3;
                        float x0=xr[0], x1=xr[1], x2=xr[2];
                        #pragma unroll
                        for (int cc=0;cc<4;++cc){
                            int c = c4*4+cc;
                            float h = fmaf(x2, sEW[c*3+2],
                                      fmaf(x1, sEW[c*3+1],
                                      fmaf(x0, sEW[c*3+0], sEB[c])));
                            if (cc==0) v.x = fmaf(av,h,v.x);
                            else if (cc==1) v.y = fmaf(av,h,v.y);
                            else if (cc==2) v.z = fmaf(av,h,v.z);
                            else v.w = fmaf(av,h,v.w);
                        }
                    }
            } else if (GCONV){
                const float4* yp = (const float4*)(Zin + ((size_t)(bt0+hb-1)*25 + gs0)*64) + c4;
                #pragma unroll
                for (int vv=0; vv<6; ++vv)
                    if (vv < n){
                        float av = sAdj[uu][vv];
                        float4 yv = yp[(size_t)vv*C4];
                        v.x += av*yv.x; v.y += av*yv.y; v.z += av*yv.z; v.w += av*yv.w;
                    }
            } else if (uu < n){
                v = ((const float4*)(Zin + ((size_t)(bt0+hb-1)*25 + gs0+uu)*64))[c4];
            }
        }
        sB4[r*PRZ + c4] = v;
    }

    unsigned long long acc[6][4];
    unsigned long long z2 = pk2(0.f, 0.f);
    #pragma unroll
    for (int i=0;i<6;++i)
        #pragma unroll
        for (int jp=0;jp<4;++jp) acc[i][jp]=z2;

    const float4* TWg = TWi + (size_t)g*3*WKT;
    for (int kt=0;kt<3;++kt){
        __syncthreads();
        for (int p=tid; p<WKT; p+=TH) sW4[p] = TWg[kt*WKT + p];
        __syncthreads();
        #pragma unroll 8
        for (int kk4=0;kk4<C4;++kk4)
            gemm_kk4<CT>(acc, sB4 + (ty+6*kt)*PRZ + kk4, 16*PRZ,
                         sWl + 2*kk4*4*CT + tx);
    }

    if (MODE==1){
        constexpr int RPASS = CRES/64;
        constexpr int RWP   = 32*4*CT;
        const float4* RWg = RWi + (size_t)g*2048;
        for (int ph=0; ph<RPASS; ++ph){
            __syncthreads();
            for (int p=tid; p<96*16; p+=TH){
                int c4l = p % 16, r = p / 16, uu = r % 6, t = r / 6;
                float4 v = make_float4(0.f,0.f,0.f,0.f);
                if (uu < n)
                    v = ((const float4*)(Yres + ((size_t)(bt0+t)*25 + gs0+uu)*CRES))[ph*16 + c4l];
                sB4[r*17 + c4l] = v;
            }
            for (int p=tid; p<RWP; p+=TH) sW4[p] = RWg[ph*RWP + p];
            __syncthreads();
            #pragma unroll 8
            for (int kk4l=0;kk4l<16;++kk4l)
                gemm_kk4<CT>(acc, sB4 + ty*17 + kk4l, 16*17, sWl + 2*kk4l*4*CT + tx);
        }
    }

    float cst[8], gsv[8], bbv[8];
    #pragma unroll
    for (int jp=0;jp<4;++jp){
        int oa = tx + CT*2*jp;
        cst[2*jp]   = CST[g*COUT+oa];       cst[2*jp+1] = CST[g*COUT+oa+CT];
        gsv[2*jp]   = GS [g*COUT+oa]*BNS;   gsv[2*jp+1] = GS [g*COUT+oa+CT]*BNS;
        bbv[2*jp]   = BB [g*COUT+oa];       bbv[2*jp+1] = BB [g*COUT+oa+CT];
    }
    #pragma unroll
    for (int i=0;i<6;++i){
        int r = ty+16*i, t = r/6, u = r%6;
        if (u < n){
            size_t base = ((size_t)(bt0+t)*25 + gs0+u)*COUT;
            int tg = t0 + t;
            bool e0 = (tg==0), e2 = (tg==NT-1);
            const float* xr = EMB ? (sX + ((t+1)*6+u)*3) : (const float*)0;
            float x0=0.f,x1=0.f,x2=0.f;
            if (EMB){ x0=xr[0]; x1=xr[1]; x2=xr[2]; }
            #pragma unroll
            for (int jp=0;jp<4;++jp){
                float lo,hi; unpk(acc[i][jp], lo, hi);
                int oa = tx + CT*2*jp;
                int ob = oa + CT;
                float pa = lo + cst[2*jp];
                float pb = hi + cst[2*jp+1];
                if (e0){ pa -= BB0[g*COUT+oa]; pb -= BB0[g*COUT+ob]; }
                if (e2){ pa -= BB2[g*COUT+oa]; pb -= BB2[g*COUT+ob]; }
                if (MODE==0){
                    if (EMB){
                        pa += fmaf(x2,sEW[oa*3+2], fmaf(x1,sEW[oa*3+1], fmaf(x0,sEW[oa*3+0], sEB[oa])));
                        pb += fmaf(x2,sEW[ob*3+2], fmaf(x1,sEW[ob*3+1], fmaf(x0,sEW[ob*3+0], sEB[ob])));
                    } else {
                        pa += Yres[base+oa]; pb += Yres[base+ob];
                    }
                }
                Yout[base+oa] = fmaxf(pa*gsv[2*jp]   + bbv[2*jp],   0.f);
                Yout[base+ob] = fmaxf(pb*gsv[2*jp+1] + bbv[2*jp+1], 0.f);
            }
        }
    }
}

__global__ __launch_bounds__(256) void k_featvq(const float* __restrict__ cb,
                                                float* __restrict__ out)
{
    int g = blockIdx.x, b = blockIdx.y;
    int tid = threadIdx.x;
    int o = tid & 63, part = tid >> 6;
    int n = c_gn[g], gs0 = c_gstart[g];
    float s = 0.f;
    int total = NT*n;
    for (int q=part; q<total; q+=4){
        int t = q / n, u = q % n;
        s += g_Y3[((size_t)(b*NT+t)*25 + gs0+u)*64 + o];
    }
    __shared__ float red[256];
    __shared__ float f[64];
    red[tid]=s; __syncthreads();
    if (part==0)
        f[o] = (red[o]+red[64+o]+red[128+o]+red[192+o]) / (float)(NT*n);
    __syncthreads();

    __shared__ float ds[128];
    __shared__ int   sidx;
    if (tid < 128){
        const float* ck = cb + (g*128 + tid)*64;
        float dot=0.f, scb=0.f;
        for (int oo=0;oo<64;++oo){ dot += f[oo]*ck[oo]; scb += ck[oo]*ck[oo]; }
        ds[tid] = scb - 2.f*dot;
    }
    __syncthreads();
    if (tid==0){
        float best = ds[0]; int bi = 0;
        for (int kk=1;kk<128;++kk) if (ds[kk] < best){ best = ds[kk]; bi = kk; }
        sidx = bi;
    }
    __syncthreads();
    int idx = sidx;
    __shared__ float dsq[64];
    if (tid < 64){
        float q = cb[(g*128 + idx)*64 + tid];
        out[(g*64+b)*64 + tid] = q;
        float dd = q - f[tid];
        dsq[tid] = dd*dd;
    }
    __syncthreads();
    if (tid==0){
        float ss=0.f;
        for (int oo=0;oo<64;++oo) ss += dsq[oo];
        g_loss[g*64+b] = 1.25f * ss / 4096.f;
        out[5*64*64 + 1 + g*64 + b] = (float)idx;
    }
}

__global__ void k_lred(float* out){
    __shared__ float s[320];
    int t = threadIdx.x;
    if (t < 320) s[t] = g_loss[t];
    __syncthreads();
    if (t==0){
        float a=0.f;
        for (int i=0;i<320;i++) a += s[i];
        out[5*64*64] = a;
    }
}

extern "C" void kernel_launch(void* const* d_in, const int* in_sizes, int n_in,
                              void* d_out, int out_size)
{
    const float* x        = (const float*)d_in[0];
    const float* embed_w  = (const float*)d_in[1];
    const float* embed_b  = (const float*)d_in[2];
    const float* sgcn_w1  = (const float*)d_in[3];
    const float* sgcn_b1  = (const float*)d_in[4];
    const float* tconv_w1 = (const float*)d_in[5];
    const float* tconv_b1 = (const float*)d_in[6];
    const float* bn_g1    = (const float*)d_in[7];
    const float* bn_b1    = (const float*)d_in[8];
    const float* res_w2   = (const float*)d_in[9];
    const float* res_b2   = (const float*)d_in[10];
    const float* resbn_g2 = (const float*)d_in[11];
    const float* resbn_b2 = (const float*)d_in[12];
    const float* sgcn_w2  = (const float*)d_in[13];
    const float* sgcn_b2  = (const float*)d_in[14];
    const float* tconv_w2 = (const float*)d_in[15];
    const float* tconv_b2 = (const float*)d_in[16];
    const float* bn_g2    = (const float*)d_in[17];
    const float* bn_b2    = (const float*)d_in[18];
    const float* res_w3   = (const float*)d_in[19];
    const float* res_b3   = (const float*)d_in[20];
    const float* resbn_g3 = (const float*)d_in[21];
    const float* resbn_b3 = (const float*)d_in[22];
    const float* sgcn_w3  = (const float*)d_in[23];
    const float* sgcn_b3  = (const float*)d_in[24];
    const float* tconv_w3 = (const float*)d_in[25];
    const float* tconv_b3 = (const float*)d_in[26];
    const float* bn_g3    = (const float*)d_in[27];
    const float* bn_b3    = (const float*)d_in[28];
    const float* codebooks= (const float*)d_in[29];
    float* out = (float*)d_out;

    void *vp;
    #define SYM(name, s, T) cudaGetSymbolAddress(&vp, s); T* name = (T*)vp;
    SYM(pZ, g_Z, float)  SYM(pY1, g_Y1, float)
    SYM(pY2, g_Y2, float)  SYM(pY3, g_Y3, float)
    SYM(pSB3,g_sb3,float)
    SYM(pC1, g_cst1,float) SYM(pB01,g_bb0_1,float) SYM(pB21,g_bb2_1,float)
    SYM(pC2, g_cst2,float) SYM(pB02,g_bb0_2,float) SYM(pB22,g_bb2_2,float)
    SYM(pC3, g_cst3,float) SYM(pZERO,g_zero,float)
    SYM(pSW3,g_sw3i,float4)
    SYM(pRW2,g_rw2i,float4) SYM(pRW3,g_rw3i,float4)
    SYM(pTW1,g_tw1i,float4) SYM(pTW2,g_tw2i,float4) SYM(pTW3,g_tw3i,float4)
    #undef SYM

    dim3 grid16(BT/16, 5);
    dim3 grid32(BT/32, 5);

    size_t emb_extra = (18*6*3 + 192 + 64)*4;        // 2.3 KB
    size_t sm_t1 = (1836 + 1024)*16 + emb_extra;     // ~48.1 KB
    size_t sm_t2 = (1836 + 2048)*16;                 // 62.1 KB
    size_t sm_t3 = (1836 + 1024)*16;                 // 45.8 KB
    size_t sm_g3 = (192*17 + 1024)*16;               // 68.6 KB

    cudaFuncSetAttribute((k_tconv<64,64,0,1,1>),   cudaFuncAttributeMaxDynamicSharedMemorySize, (int)sm_t1);
    cudaFuncSetAttribute((k_tconv<128,64,1,1,0>),  cudaFuncAttributeMaxDynamicSharedMemorySize, (int)sm_t2);
    cudaFuncSetAttribute(k_gcn3,                   cudaFuncAttributeMaxDynamicSharedMemorySize, (int)sm_g3);
    cudaFuncSetAttribute((k_tconv<64,128,1,0,0>),  cudaFuncAttributeMaxDynamicSharedMemorySize, (int)sm_t3);

    k_prep<<<64,256>>>(sgcn_w1, sgcn_b1, tconv_w1, tconv_b1,
                       res_w2, res_b2, resbn_g2, resbn_b2, sgcn_w2, sgcn_b2, tconv_w2, tconv_b2,
                       res_w3, res_b3, resbn_g3, resbn_b3, sgcn_w3, sgcn_b3, tconv_w3, tconv_b3);

    // Layer 1: embed + graph conv + composite tconv + identity residual, all fused
    k_tconv<64,64,0,1,1><<<grid16,128,sm_t1>>>(x, x, pY1, pTW1, pRW2,
                                               pC1, pB01, pB21, bn_g1, bn_b1,
                                               embed_w, embed_b);
    // Layer 2: fused graph conv + composite tconv (128 out), residual from Y1
    k_tconv<128,64,1,1,0><<<grid16,256,sm_t2>>>(pY1, pY1, pY2, pTW2, pRW2,
                                                pC2, pB02, pB22, bn_g2, bn_b2,
                                                nullptr, nullptr);
    // Layer 3
    k_gcn3<<<grid32,256,sm_g3>>>(pY2, pZ, pSW3, pSB3);
    k_tconv<64,128,1,0,0><<<grid16,128,sm_t3>>>(pZ, pY2, pY3, pTW3, pRW3,
                                                pC3, pZERO, pZERO, bn_g3, bn_b3,
                                                nullptr, nullptr);

    k_featvq<<<dim3(5,64),256>>>(codebooks, out);
    k_lred<<<1,512>>>(out);
}

// round 13
// speedup vs baseline: 1.2056x; 1.0618x over previous
#include <cuda_runtime.h>

#define NB 64
#define NT 256
#define BT (NB*NT)
#define BNS 0.9999950000374997f

__constant__ int c_s2j[25] = {0,1,2,3,20, 4,5,6,7,21,22, 8,9,10,11,23,24, 12,13,14,15, 16,17,18,19};
__constant__ int c_gstart[5] = {0,5,11,17,21};
__constant__ int c_gn[5]     = {5,6,6,4,4};

__device__ float g_adj[5][6][6];
__device__ float g_Z [BT*25*64];
__device__ float g_Y1[BT*25*64];
__device__ float g_Y2[BT*25*128];
__device__ float g_Y3[BT*25*64];
__device__ float g_loss[5*64];
__device__ float g_sb3[5*64];
__device__ float g_cst1[5*64],  g_bb0_1[5*64],  g_bb2_1[5*64];
__device__ float g_cst2[5*128], g_bb0_2[5*128], g_bb2_2[5*128];
__device__ float g_cst3[5*64];
__device__ float g_zero[640];
__device__ float4 g_sw3i[10240];
__device__ float4 g_rw2i[10240];
__device__ float4 g_rw3i[10240];
__device__ float4 g_tw1i[15360];
__device__ float4 g_tw2i[30720];
__device__ float4 g_tw3i[15360];

__device__ __forceinline__ unsigned long long bc2(float x){
    unsigned long long r; unsigned u = __float_as_uint(x);
    asm("mov.b64 %0, {%1, %1};" : "=l"(r) : "r"(u));
    return r;
}
__device__ __forceinline__ unsigned long long pk2(float a, float b){
    unsigned long long r;
    asm("mov.b64 %0, {%1, %2};" : "=l"(r) : "r"(__float_as_uint(a)), "r"(__float_as_uint(b)));
    return r;
}
__device__ __forceinline__ void ffma2(unsigned long long& c, unsigned long long a, unsigned long long b){
    asm("fma.rn.f32x2 %0, %1, %2, %0;" : "+l"(c) : "l"(a), "l"(b));
}
__device__ __forceinline__ void unpk(unsigned long long v, float& lo, float& hi){
    unsigned a,b; asm("mov.b64 {%0, %1}, %2;" : "=r"(a), "=r"(b) : "l"(v));
    lo = __uint_as_float(a); hi = __uint_as_float(b);
}

__global__ __launch_bounds__(256) void k_prep(
    const float* __restrict__ sw1, const float* __restrict__ sb1,
    const float* __restrict__ tw1, const float* __restrict__ tb1,
    const float* __restrict__ rw2, const float* __restrict__ rb2,
    const float* __restrict__ rg2, const float* __restrict__ rbb2,
    const float* __restrict__ sw2, const float* __restrict__ sb2,
    const float* __restrict__ tw2, const float* __restrict__ tb2,
    const float* __restrict__ rw3, const float* __restrict__ rb3,
    const float* __restrict__ rg3, const float* __restrict__ rbb3,
    const float* __restrict__ sw3, const float* __restrict__ sb3,
    const float* __restrict__ tw3, const float* __restrict__ tb3)
{
    int gt  = blockIdx.x*blockDim.x + threadIdx.x;
    int NTH = gridDim.x*blockDim.x;

    for (int e=gt;e<15360;e+=NTH){
        int g=e/3072, r=e%3072, kt=r/1024, r2=r%1024, kk2=r2/32, q=r2%32, jp=q/8, tx=q%8;
        int oa=tx+16*jp, ob=oa+8, k0=2*kk2;
        float v0=0.f,v1=0.f,v2=0.f,v3=0.f;
        for (int c=0;c<64;c++){
            float s0 = sw1[(g*192+c)*64+k0]   + sw1[(g*192+64+c)*64+k0]   + sw1[(g*192+128+c)*64+k0];
            float s1 = sw1[(g*192+c)*64+k0+1] + sw1[(g*192+64+c)*64+k0+1] + sw1[(g*192+128+c)*64+k0+1];
            float wa = tw1[((g*64+oa)*64+c)*3+kt];
            float wb = tw1[((g*64+ob)*64+c)*3+kt];
            v0=fmaf(wa,s0,v0); v1=fmaf(wb,s0,v1); v2=fmaf(wa,s1,v2); v3=fmaf(wb,s1,v3);
        }
        g_tw1i[e]=make_float4(v0,v1,v2,v3);
    }
    for (int e=gt;e<15360;e+=NTH){
        int g=e/3072, r=e%3072, kt=r/1024, r2=r%1024, kk2=r2/32, q=r2%32, jp=q/8, tx=q%8;
        int oa=tx+16*jp, ob=oa+8, k0=2*kk2;
        g_tw3i[e]=make_float4(tw3[((g*64+oa)*64+k0)*3+kt],   tw3[((g*64+ob)*64+k0)*3+kt],
                              tw3[((g*64+oa)*64+k0+1)*3+kt], tw3[((g*64+ob)*64+k0+1)*3+kt]);
    }
    for (int e=gt;e<30720;e+=NTH){
        int g=e/6144, r=e%6144, kt=r/2048, r2=r%2048, kk2=r2/64, q=r2%64, jp=q/16, tx=q%16;
        int oa=tx+32*jp, ob=oa+16, k0=2*kk2;
        float v0=0.f,v1=0.f,v2=0.f,v3=0.f;
        for (int c=0;c<128;c++){
            float s0 = sw2[(g*384+c)*64+k0]   + sw2[(g*384+128+c)*64+k0]   + sw2[(g*384+256+c)*64+k0];
            float s1 = sw2[(g*384+c)*64+k0+1] + sw2[(g*384+128+c)*64+k0+1] + sw2[(g*384+256+c)*64+k0+1];
            float wa = tw2[((g*128+oa)*128+c)*3+kt];
            float wb = tw2[((g*128+ob)*128+c)*3+kt];
            v0=fmaf(wa,s0,v0); v1=fmaf(wb,s0,v1); v2=fmaf(wa,s1,v2); v3=fmaf(wb,s1,v3);
        }
        g_tw2i[e]=make_float4(v0,v1,v2,v3);
    }
    for (int e=gt;e<10240;e+=NTH){
        int g=e/2048, r=e%2048, kk2=r/32, q=r%32, jp=q/8, tx=q%8;
        int oa=tx+16*jp, ob=oa+8, k0=2*kk2;
        const float* w = sw3 + g*192*128;
        #define S3(o,c) (w[(o)*128+(c)] + w[(64+(o))*128+(c)] + w[(128+(o))*128+(c)])
        g_sw3i[e] = make_float4(S3(oa,k0), S3(ob,k0), S3(oa,k0+1), S3(ob,k0+1));
        #undef S3
    }
    for (int e=gt;e<10240;e+=NTH){
        int g=e/2048, r=e%2048, kk2=r/64, q=r%64, jp=q/16, tx=q%16;
        int oa=tx+32*jp, ob=oa+16, k0=2*kk2;
        const float* w = rw2 + g*8192;
        float sa_=rg2[g*128+oa]*BNS, sb_=rg2[g*128+ob]*BNS;
        g_rw2i[e] = make_float4(w[oa*64+k0]*sa_, w[ob*64+k0]*sb_, w[oa*64+k0+1]*sa_, w[ob*64+k0+1]*sb_);
    }
    for (int e=gt;e<10240;e+=NTH){
        int g=e/2048, r=e%2048, kk2=r/32, q=r%32, jp=q/8, tx=q%8;
        int oa=tx+16*jp, ob=oa+8, k0=2*kk2;
        const float* w = rw3 + g*8192;
        float sa_=rg3[g*64+oa]*BNS, sb_=rg3[g*64+ob]*BNS;
        g_rw3i[e] = make_float4(w[oa*128+k0]*sa_, w[ob*128+k0]*sb_, w[oa*128+k0+1]*sa_, w[ob*128+k0+1]*sb_);
    }
    for (int i=gt;i<5*64;i+=NTH){
        int g=i/64, o=i%64;
        float b0=0.f,b1=0.f,b2=0.f;
        for (int c=0;c<64;c++){
            float sb = sb1[g*192+c]+sb1[g*192+64+c]+sb1[g*192+128+c];
            b0=fmaf(tw1[((g*64+o)*64+c)*3+0],sb,b0);
            b1=fmaf(tw1[((g*64+o)*64+c)*3+1],sb,b1);
            b2=fmaf(tw1[((g*64+o)*64+c)*3+2],sb,b2);
        }
        g_cst1[i]=tb1[i]+b0+b1+b2;
        g_bb0_1[i]=b0; g_bb2_1[i]=b2;
        const float* s3=sb3+g*192;
        g_sb3[i]=s3[o]+s3[64+o]+s3[128+o];
        g_cst3[i]=tb3[i]+rb3[i]*rg3[i]*BNS+rbb3[i];
    }
    for (int i=gt;i<5*128;i+=NTH){
        int g=i/128, o=i%128;
        float b0=0.f,b1=0.f,b2=0.f;
        for (int c=0;c<128;c++){
            float sb = sb2[g*384+c]+sb2[g*384+128+c]+sb2[g*384+256+c];
            b0=fmaf(tw2[((g*128+o)*128+c)*3+0],sb,b0);
            b1=fmaf(tw2[((g*128+o)*128+c)*3+1],sb,b1);
            b2=fmaf(tw2[((g*128+o)*128+c)*3+2],sb,b2);
        }
        g_cst2[i]=tb2[i]+rb2[i]*rg2[i]*BNS+rbb2[i]+b0+b1+b2;
        g_bb0_2[i]=b0; g_bb2_2[i]=b2;
    }
    for (int i=gt;i<640;i+=NTH) g_zero[i]=0.f;
    if (gt==0){
        double fa[25][25];
        for (int i=0;i<25;i++) for (int j=0;j<25;j++) fa[i][j]=0.0;
        const int E[24][2]={{3,2},{2,20},{20,1},{1,0},{20,4},{4,5},{5,6},{6,22},
                            {6,7},{7,21},{20,8},{8,9},{9,10},{10,24},{10,11},{11,23},
                            {0,12},{12,13},{13,14},{14,15},{0,16},{16,17},{17,18},{18,19}};
        for (int k=0;k<24;k++){
            int i=E[k][0]-1, j=E[k][1]-1;
            fa[i][j]=1.0; fa[j][i]=1.0;
        }
        for (int i=0;i<25;i++) fa[i][i]+=1.0;
        for (int i=0;i<25;i++){
            double d=0; for (int j=0;j<25;j++) d+=fa[i][j];
            if (d==0.0) d=1.0;
            for (int j=0;j<25;j++) fa[i][j]/=d;
        }
        for (int g=0;g<5;g++){
            int n=c_gn[g];
            int js[6]; for (int u=0;u<n;u++) js[u]=c_s2j[c_gstart[g]+u];
            double sa[6][6];
            for (int u=0;u<n;u++) for (int v=0;v<n;v++) sa[u][v]=fa[js[u]][js[v]];
            for (int u=0;u<n;u++) sa[u][u]+=1.0;
            double dg[6];
            for (int u=0;u<n;u++){ double d=0; for (int v=0;v<n;v++) d+=sa[u][v]; dg[u]=d; }
            for (int node=1;node<n;node++)
                if (dg[node]==1.0){ sa[0][node]=1.0; sa[node][0]=1.0; }
            for (int u=0;u<6;u++) for (int v=0;v<6;v++){
                float val=0.f;
                if (u<n && v<n){
                    double d=0; for (int w=0;w<n;w++) d+=sa[u][w];
                    if (d==0.0) d=1.0;
                    val=(float)(sa[u][v]/d);
                }
                g_adj[g][u][v]=val;
            }
        }
    }
}

template<int CT>
__device__ __forceinline__ void gemm_kk4(unsigned long long (&acc)[6][4],
                                         const float4* aPtr, int aStride,
                                         const ulonglong2* wPtr)
{
    float4 a[6];
    #pragma unroll
    for (int i=0;i<6;++i) a[i] = aPtr[aStride*i];
    #pragma unroll
    for (int h=0;h<2;++h){
        ulonglong2 w0 = wPtr[h*4*CT + 0*CT];
        ulonglong2 w1 = wPtr[h*4*CT + 1*CT];
        ulonglong2 w2 = wPtr[h*4*CT + 2*CT];
        ulonglong2 w3 = wPtr[h*4*CT + 3*CT];
        #pragma unroll
        for (int i=0;i<6;++i){
            unsigned long long alo = bc2(h ? a[i].z : a[i].x);
            unsigned long long ahi = bc2(h ? a[i].w : a[i].y);
            ffma2(acc[i][0], alo, w0.x);
            ffma2(acc[i][1], alo, w1.x);
            ffma2(acc[i][2], alo, w2.x);
            ffma2(acc[i][3], alo, w3.x);
            ffma2(acc[i][0], ahi, w0.y);
            ffma2(acc[i][1], ahi, w1.y);
            ffma2(acc[i][2], ahi, w2.y);
            ffma2(acc[i][3], ahi, w3.y);
        }
    }
}

// Layer-3 GCN: staging gathers each (t,c4) once, produces all 6 slots.
__global__ __launch_bounds__(256) void k_gcn3(const float* __restrict__ Y,
                                              float* __restrict__ Z,
                                              const float4* __restrict__ Wi,
                                              const float* __restrict__ Bv)
{
    constexpr int CT = 8;
    extern __shared__ float sm[];
    float4* sA4 = (float4*)sm;
    float4* sW4 = sA4 + 192*17;
    const ulonglong2* sWl = (const ulonglong2*)sW4;
    __shared__ float sAdj[6][6];

    const int g   = blockIdx.y;
    const int n   = c_gn[g];
    const int gs0 = c_gstart[g];
    const int bt0 = blockIdx.x * 32;
    const int tid = threadIdx.x;
    if (tid < 36) sAdj[tid/6][tid%6] = g_adj[g][tid/6][tid%6];

    const int ty = tid / CT, tx = tid % CT;
    unsigned long long acc[6][4];
    #pragma unroll
    for (int jp=0;jp<4;++jp){
        int oa = tx + 16*jp;
        unsigned long long b2 = pk2(Bv[g*64+oa], Bv[g*64+oa+8]);
        #pragma unroll
        for (int i=0;i<6;++i) acc[i][jp]=b2;
    }
    const float4* Wg = Wi + (size_t)g*2048;

    for (int ph=0; ph<2; ++ph){
        __syncthreads();
        for (int p=tid; p<32*16; p+=256){
            int c4l = p % 16, t = p / 16;
            int c4 = ph*16 + c4l;
            const float4* yp = (const float4*)(Y + ((size_t)(bt0+t)*25 + gs0)*128) + c4;
            float4 yv[6];
            #pragma unroll
            for (int vv=0; vv<6; ++vv)
                yv[vv] = (vv < n) ? yp[(size_t)vv*32] : make_float4(0.f,0.f,0.f,0.f);
            #pragma unroll
            for (int uu=0; uu<6; ++uu){
                float4 v = make_float4(0.f,0.f,0.f,0.f);
                #pragma unroll
                for (int vv=0; vv<6; ++vv)
                    if (vv < n){
                        float av = sAdj[uu][vv];
                        v.x += av*yv[vv].x; v.y += av*yv[vv].y;
                        v.z += av*yv[vv].z; v.w += av*yv[vv].w;
                    }
                sA4[(t*6+uu)*17 + c4l] = v;
            }
        }
        for (int p=tid; p<1024; p+=256) sW4[p] = Wg[ph*1024 + p];
        __syncthreads();
        #pragma unroll 8
        for (int kk4l=0;kk4l<16;++kk4l)
            gemm_kk4<CT>(acc, sA4 + ty*17 + kk4l, 32*17, sWl + 2*kk4l*4*CT + tx);
    }

    #pragma unroll
    for (int i=0;i<6;++i){
        int r = ty+32*i, t = r/6, u = r%6;
        if (u < n){
            float* zp = Z + ((size_t)(bt0+t)*25 + gs0+u)*64;
            #pragma unroll
            for (int jp=0;jp<4;++jp){
                float lo,hi; unpk(acc[i][jp], lo, hi);
                int oa = tx + 16*jp;
                zp[oa] = lo; zp[oa+8] = hi;
            }
        }
    }
}

// tconv: TBL=16, per-kt W staging; GCONV/EMB staging gathers once per (hb,c4).
template<int COUT,int CRES,int MODE,int GCONV,int EMB>
__global__ __launch_bounds__((COUT/8)*16)
void k_tconv(const float* __restrict__ Zin, const float* __restrict__ Yres,
             float* __restrict__ Yout,
             const float4* __restrict__ TWi, const float4* __restrict__ RWi,
             const float* __restrict__ CST, const float* __restrict__ BB0,
             const float* __restrict__ BB2,
             const float* __restrict__ GS, const float* __restrict__ BB,
             const float* __restrict__ EW, const float* __restrict__ EB)
{
    constexpr int CT  = COUT/8;
    constexpr int TH  = CT*16;
    constexpr int C4  = 16;
    constexpr int PRZ = 17;
    constexpr int TBL = 16;
    constexpr int WKT = 32*4*CT;
    constexpr int SBUF4 = (TBL+2)*6*PRZ;    // 1836
    extern __shared__ float sm[];
    float4* sB4 = (float4*)sm;
    float4* sW4 = sB4 + SBUF4;
    const ulonglong2* sWl = (const ulonglong2*)sW4;
    float* sX  = (float*)(sW4 + WKT);       // [18*6*3] (EMB only)
    float* sEW = sX + 18*6*3;               // [192]
    float* sEB = sEW + 192;                 // [64]
    __shared__ float sAdj[6][6];

    const int g   = blockIdx.y;
    const int n   = c_gn[g];
    const int gs0 = c_gstart[g];
    const int bt0 = blockIdx.x * TBL;
    const int t0  = bt0 & (NT-1);
    const int tid = threadIdx.x, ty = tid/CT, tx = tid%CT;

    if (GCONV){
        if (tid < 36) sAdj[tid/6][tid%6] = g_adj[g][tid/6][tid%6];
    }
    if (EMB){
        for (int p=tid; p<192; p+=TH) sEW[p] = EW[p];
        for (int p=tid; p<64;  p+=TH) sEB[p] = EB[p];
        for (int p=tid; p<18*6; p+=TH){
            int u = p % 6, hb = p / 6;
            int t = t0 + hb - 1;
            float x0=0.f,x1=0.f,x2=0.f;
            if (t >= 0 && t < NT && u < n){
                int j = c_s2j[gs0+u];
                const float* xp = Zin + ((size_t)(bt0+hb-1)*25 + j)*3;
                x0=xp[0]; x1=xp[1]; x2=xp[2];
            }
            sX[p*3+0]=x0; sX[p*3+1]=x1; sX[p*3+2]=x2;
        }
    }
    if (GCONV || EMB) __syncthreads();

    if (EMB){
        for (int p=tid; p<(TBL+2)*C4; p+=TH){
            int c4 = p % C4, hb = p / C4;
            int t = t0 + hb - 1;
            bool valid = (t >= 0 && t < NT);
            float h[6][4];
            if (valid){
                #pragma unroll
                for (int vv=0; vv<6; ++vv){
                    const float* xr = sX + (hb*6+vv)*3;
                    float x0=xr[0], x1=xr[1], x2=xr[2];
                    #pragma unroll
                    for (int cc=0;cc<4;++cc){
                        int c = c4*4+cc;
                        h[vv][cc] = fmaf(x2, sEW[c*3+2],
                                    fmaf(x1, sEW[c*3+1],
                                    fmaf(x0, sEW[c*3+0], sEB[c])));
                    }
                }
            }
            #pragma unroll
            for (int uu=0; uu<6; ++uu){
                float4 v = make_float4(0.f,0.f,0.f,0.f);
                if (valid){
                    #pragma unroll
                    for (int vv=0; vv<6; ++vv)
                        if (vv < n){
                            float av = sAdj[uu][vv];
                            v.x = fmaf(av,h[vv][0],v.x);
                            v.y = fmaf(av,h[vv][1],v.y);
                            v.z = fmaf(av,h[vv][2],v.z);
                            v.w = fmaf(av,h[vv][3],v.w);
                        }
                }
                sB4[(hb*6+uu)*PRZ + c4] = v;
            }
        }
    } else if (GCONV){
        for (int p=tid; p<(TBL+2)*C4; p+=TH){
            int c4 = p % C4, hb = p / C4;
            int t = t0 + hb - 1;
            bool valid = (t >= 0 && t < NT);
            float4 yv[6];
            if (valid){
                const float4* yp = (const float4*)(Zin + ((size_t)(bt0+hb-1)*25 + gs0)*64) + c4;
                #pragma unroll
                for (int vv=0; vv<6; ++vv)
                    yv[vv] = (vv < n) ? yp[(size_t)vv*C4] : make_float4(0.f,0.f,0.f,0.f);
            }
            #pragma unroll
            for (int uu=0; uu<6; ++uu){
                float4 v = make_float4(0.f,0.f,0.f,0.f);
                if (valid){
                    #pragma unroll
                    for (int vv=0; vv<6; ++vv)
                        if (vv < n){
                            float av = sAdj[uu][vv];
                            v.x += av*yv[vv].x; v.y += av*yv[vv].y;
                            v.z += av*yv[vv].z; v.w += av*yv[vv].w;
                        }
                }
                sB4[(hb*6+uu)*PRZ + c4] = v;
            }
        }
    } else {
        for (int p=tid; p<(TBL+2)*6*C4; p+=TH){
            int c4 = p % C4, r = p / C4, uu = r % 6, hb = r / 6;
            int t = t0 + hb - 1;
            float4 v = make_float4(0.f,0.f,0.f,0.f);
            if (t >= 0 && t < NT && uu < n)
                v = ((const float4*)(Zin + ((size_t)(bt0+hb-1)*25 + gs0+uu)*64))[c4];
            sB4[r*PRZ + c4] = v;
        }
    }

    unsigned long long acc[6][4];
    unsigned long long z2 = pk2(0.f, 0.f);
    #pragma unroll
    for (int i=0;i<6;++i)
        #pragma unroll
        for (int jp=0;jp<4;++jp) acc[i][jp]=z2;

    const float4* TWg = TWi + (size_t)g*3*WKT;
    for (int kt=0;kt<3;++kt){
        __syncthreads();
        for (int p=tid; p<WKT; p+=TH) sW4[p] = TWg[kt*WKT + p];
        __syncthreads();
        #pragma unroll 8
        for (int kk4=0;kk4<C4;++kk4)
            gemm_kk4<CT>(acc, sB4 + (ty+6*kt)*PRZ + kk4, 16*PRZ,
                         sWl + 2*kk4*4*CT + tx);
    }

    if (MODE==1){
        constexpr int RPASS = CRES/64;
        constexpr int RWP   = 32*4*CT;
        const float4* RWg = RWi + (size_t)g*2048;
        for (int ph=0; ph<RPASS; ++ph){
            __syncthreads();
            for (int p=tid; p<96*16; p+=TH){
                int c4l = p % 16, r = p / 16, uu = r % 6, t = r / 6;
                float4 v = make_float4(0.f,0.f,0.f,0.f);
                if (uu < n)
                    v = ((const float4*)(Yres + ((size_t)(bt0+t)*25 + gs0+uu)*CRES))[ph*16 + c4l];
                sB4[r*17 + c4l] = v;
            }
            for (int p=tid; p<RWP; p+=TH) sW4[p] = RWg[ph*RWP + p];
            __syncthreads();
            #pragma unroll 8
            for (int kk4l=0;kk4l<16;++kk4l)
                gemm_kk4<CT>(acc, sB4 + ty*17 + kk4l, 16*17, sWl + 2*kk4l*4*CT + tx);
        }
    }

    float cst[8], gsv[8], bbv[8];
    #pragma unroll
    for (int jp=0;jp<4;++jp){
        int oa = tx + CT*2*jp;
        cst[2*jp]   = CST[g*COUT+oa];       cst[2*jp+1] = CST[g*COUT+oa+CT];
        gsv[2*jp]   = GS [g*COUT+oa]*BNS;   gsv[2*jp+1] = GS [g*COUT+oa+CT]*BNS;
        bbv[2*jp]   = BB [g*COUT+oa];       bbv[2*jp+1] = BB [g*COUT+oa+CT];
    }
    #pragma unroll
    for (int i=0;i<6;++i){
        int r = ty+16*i, t = r/6, u = r%6;
        if (u < n){
            size_t base = ((size_t)(bt0+t)*25 + gs0+u)*COUT;
            int tg = t0 + t;
            bool e0 = (tg==0), e2 = (tg==NT-1);
            const float* xr = EMB ? (sX + ((t+1)*6+u)*3) : (const float*)0;
            float x0=0.f,x1=0.f,x2=0.f;
            if (EMB){ x0=xr[0]; x1=xr[1]; x2=xr[2]; }
            #pragma unroll
            for (int jp=0;jp<4;++jp){
                float lo,hi; unpk(acc[i][jp], lo, hi);
                int oa = tx + CT*2*jp;
                int ob = oa + CT;
                float pa = lo + cst[2*jp];
                float pb = hi + cst[2*jp+1];
                if (e0){ pa -= BB0[g*COUT+oa]; pb -= BB0[g*COUT+ob]; }
                if (e2){ pa -= BB2[g*COUT+oa]; pb -= BB2[g*COUT+ob]; }
                if (MODE==0){
                    if (EMB){
                        pa += fmaf(x2,sEW[oa*3+2], fmaf(x1,sEW[oa*3+1], fmaf(x0,sEW[oa*3+0], sEB[oa])));
                        pb += fmaf(x2,sEW[ob*3+2], fmaf(x1,sEW[ob*3+1], fmaf(x0,sEW[ob*3+0], sEB[ob])));
                    } else {
                        pa += Yres[base+oa]; pb += Yres[base+ob];
                    }
                }
                Yout[base+oa] = fmaxf(pa*gsv[2*jp]   + bbv[2*jp],   0.f);
                Yout[base+ob] = fmaxf(pb*gsv[2*jp+1] + bbv[2*jp+1], 0.f);
            }
        }
    }
}

__global__ __launch_bounds__(256) void k_featvq(const float* __restrict__ cb,
                                                float* __restrict__ out)
{
    int g = blockIdx.x, b = blockIdx.y;
    int tid = threadIdx.x;
    int o = tid & 63, part = tid >> 6;
    int n = c_gn[g], gs0 = c_gstart[g];
    float s = 0.f;
    int total = NT*n;
    for (int q=part; q<total; q+=4){
        int t = q / n, u = q % n;
        s += g_Y3[((size_t)(b*NT+t)*25 + gs0+u)*64 + o];
    }
    __shared__ float red[256];
    __shared__ float f[64];
    red[tid]=s; __syncthreads();
    if (part==0)
        f[o] = (red[o]+red[64+o]+red[128+o]+red[192+o]) / (float)(NT*n);
    __syncthreads();

    __shared__ float ds[128];
    __shared__ int   sidx;
    if (tid < 128){
        const float* ck = cb + (g*128 + tid)*64;
        float dot=0.f, scb=0.f;
        for (int oo=0;oo<64;++oo){ dot += f[oo]*ck[oo]; scb += ck[oo]*ck[oo]; }
        ds[tid] = scb - 2.f*dot;
    }
    __syncthreads();
    if (tid==0){
        float best = ds[0]; int bi = 0;
        for (int kk=1;kk<128;++kk) if (ds[kk] < best){ best = ds[kk]; bi = kk; }
        sidx = bi;
    }
    __syncthreads();
    int idx = sidx;
    __shared__ float dsq[64];
    if (tid < 64){
        float q = cb[(g*128 + idx)*64 + tid];
        out[(g*64+b)*64 + tid] = q;
        float dd = q - f[tid];
        dsq[tid] = dd*dd;
    }
    __syncthreads();
    if (tid==0){
        float ss=0.f;
        for (int oo=0;oo<64;++oo) ss += dsq[oo];
        g_loss[g*64+b] = 1.25f * ss / 4096.f;
        out[5*64*64 + 1 + g*64 + b] = (float)idx;
    }
}

__global__ void k_lred(float* out){
    __shared__ float s[320];
    int t = threadIdx.x;
    if (t < 320) s[t] = g_loss[t];
    __syncthreads();
    if (t==0){
        float a=0.f;
        for (int i=0;i<320;i++) a += s[i];
        out[5*64*64] = a;
    }
}

extern "C" void kernel_launch(void* const* d_in, const int* in_sizes, int n_in,
                              void* d_out, int out_size)
{
    const float* x        = (const float*)d_in[0];
    const float* embed_w  = (const float*)d_in[1];
    const float* embed_b  = (const float*)d_in[2];
    const float* sgcn_w1  = (const float*)d_in[3];
    const float* sgcn_b1  = (const float*)d_in[4];
    const float* tconv_w1 = (const float*)d_in[5];
    const float* tconv_b1 = (const float*)d_in[6];
    const float* bn_g1    = (const float*)d_in[7];
    const float* bn_b1    = (const float*)d_in[8];
    const float* res_w2   = (const float*)d_in[9];
    const float* res_b2   = (const float*)d_in[10];
    const float* resbn_g2 = (const float*)d_in[11];
    const float* resbn_b2 = (const float*)d_in[12];
    const float* sgcn_w2  = (const float*)d_in[13];
    const float* sgcn_b2  = (const float*)d_in[14];
    const float* tconv_w2 = (const float*)d_in[15];
    const float* tconv_b2 = (const float*)d_in[16];
    const float* bn_g2    = (const float*)d_in[17];
    const float* bn_b2    = (const float*)d_in[18];
    const float* res_w3   = (const float*)d_in[19];
    const float* res_b3   = (const float*)d_in[20];
    const float* resbn_g3 = (const float*)d_in[21];
    const float* resbn_b3 = (const float*)d_in[22];
    const float* sgcn_w3  = (const float*)d_in[23];
    const float* sgcn_b3  = (const float*)d_in[24];
    const float* tconv_w3 = (const float*)d_in[25];
    const float* tconv_b3 = (const float*)d_in[26];
    const float* bn_g3    = (const float*)d_in[27];
    const float* bn_b3    = (const float*)d_in[28];
    const float* codebooks= (const float*)d_in[29];
    float* out = (float*)d_out;

    void *vp;
    #define SYM(name, s, T) cudaGetSymbolAddress(&vp, s); T* name = (T*)vp;
    SYM(pZ, g_Z, float)  SYM(pY1, g_Y1, float)
    SYM(pY2, g_Y2, float)  SYM(pY3, g_Y3, float)
    SYM(pSB3,g_sb3,float)
    SYM(pC1, g_cst1,float) SYM(pB01,g_bb0_1,float) SYM(pB21,g_bb2_1,float)
    SYM(pC2, g_cst2,float) SYM(pB02,g_bb0_2,float) SYM(pB22,g_bb2_2,float)
    SYM(pC3, g_cst3,float) SYM(pZERO,g_zero,float)
    SYM(pSW3,g_sw3i,float4)
    SYM(pRW2,g_rw2i,float4) SYM(pRW3,g_rw3i,float4)
    SYM(pTW1,g_tw1i,float4) SYM(pTW2,g_tw2i,float4) SYM(pTW3,g_tw3i,float4)
    #undef SYM

    dim3 grid16(BT/16, 5);
    dim3 grid32(BT/32, 5);

    size_t emb_extra = (18*6*3 + 192 + 64)*4;
    size_t sm_t1 = (1836 + 1024)*16 + emb_extra;
    size_t sm_t2 = (1836 + 2048)*16;
    size_t sm_t3 = (1836 + 1024)*16;
    size_t sm_g3 = (192*17 + 1024)*16;

    cudaFuncSetAttribute((k_tconv<64,64,0,1,1>),   cudaFuncAttributeMaxDynamicSharedMemorySize, (int)sm_t1);
    cudaFuncSetAttribute((k_tconv<128,64,1,1,0>),  cudaFuncAttributeMaxDynamicSharedMemorySize, (int)sm_t2);
    cudaFuncSetAttribute(k_gcn3,                   cudaFuncAttributeMaxDynamicSharedMemorySize, (int)sm_g3);
    cudaFuncSetAttribute((k_tconv<64,128,1,0,0>),  cudaFuncAttributeMaxDynamicSharedMemorySize, (int)sm_t3);

    k_prep<<<64,256>>>(sgcn_w1, sgcn_b1, tconv_w1, tconv_b1,
                       res_w2, res_b2, resbn_g2, resbn_b2, sgcn_w2, sgcn_b2, tconv_w2, tconv_b2,
                       res_w3, res_b3, resbn_g3, resbn_b3, sgcn_w3, sgcn_b3, tconv_w3, tconv_b3);

    k_tconv<64,64,0,1,1><<<grid16,128,sm_t1>>>(x, x, pY1, pTW1, pRW2,
                                               pC1, pB01, pB21, bn_g1, bn_b1,
                                               embed_w, embed_b);
    k_tconv<128,64,1,1,0><<<grid16,256,sm_t2>>>(pY1, pY1, pY2, pTW2, pRW2,
                                                pC2, pB02, pB22, bn_g2, bn_b2,
                                                nullptr, nullptr);
    k_gcn3<<<grid32,256,sm_g3>>>(pY2, pZ, pSW3, pSB3);
    k_tconv<64,128,1,0,0><<<grid16,128,sm_t3>>>(pZ, pY2, pY3, pTW3, pRW3,
                                                pC3, pZERO, pZERO, bn_g3, bn_b3,
                                                nullptr, nullptr);

    k_featvq<<<dim3(5,64),256>>>(codebooks, out);
    k_lred<<<1,512>>>(out);
}

// round 14
// speedup vs baseline: 1.2487x; 1.0358x over previous
#include <cuda_runtime.h>

#define NB 64
#define NT 256
#define BT (NB*NT)
#define BNS 0.9999950000374997f

__constant__ int c_s2j[25] = {0,1,2,3,20, 4,5,6,7,21,22, 8,9,10,11,23,24, 12,13,14,15, 16,17,18,19};
__constant__ int c_gstart[5] = {0,5,11,17,21};
__constant__ int c_gn[5]     = {5,6,6,4,4};

__device__ float g_adj[5][6][6];
__device__ float g_Z [BT*25*64];
__device__ float g_Y1[BT*25*64];
__device__ float g_Y2[BT*25*128];
__device__ float g_Y3[BT*25*64];
__device__ float g_loss[5*64];
__device__ float g_sb3[5*64];
__device__ float g_cst1[5*64],  g_bb0_1[5*64],  g_bb2_1[5*64];
__device__ float g_cst2[5*128], g_bb0_2[5*128], g_bb2_2[5*128];
__device__ float g_cst3[5*64];
__device__ float g_zero[640];
__device__ float4 g_sw3i[10240];
__device__ float4 g_rw2i[10240];
__device__ float4 g_rw3i[10240];
__device__ float4 g_tw1i[15360];
__device__ float4 g_tw2i[30720];
__device__ float4 g_tw3i[15360];

__device__ __forceinline__ unsigned long long bc2(float x){
    unsigned long long r; unsigned u = __float_as_uint(x);
    asm("mov.b64 %0, {%1, %1};" : "=l"(r) : "r"(u));
    return r;
}
__device__ __forceinline__ unsigned long long pk2(float a, float b){
    unsigned long long r;
    asm("mov.b64 %0, {%1, %2};" : "=l"(r) : "r"(__float_as_uint(a)), "r"(__float_as_uint(b)));
    return r;
}
__device__ __forceinline__ void ffma2(unsigned long long& c, unsigned long long a, unsigned long long b){
    asm("fma.rn.f32x2 %0, %1, %2, %0;" : "+l"(c) : "l"(a), "l"(b));
}
__device__ __forceinline__ void unpk(unsigned long long v, float& lo, float& hi){
    unsigned a,b; asm("mov.b64 {%0, %1}, %2;" : "=r"(a), "=r"(b) : "l"(v));
    lo = __uint_as_float(a); hi = __uint_as_float(b);
}

__global__ __launch_bounds__(256) void k_prep(
    const float* __restrict__ sw1, const float* __restrict__ sb1,
    const float* __restrict__ tw1, const float* __restrict__ tb1,
    const float* __restrict__ rw2, const float* __restrict__ rb2,
    const float* __restrict__ rg2, const float* __restrict__ rbb2,
    const float* __restrict__ sw2, const float* __restrict__ sb2,
    const float* __restrict__ tw2, const float* __restrict__ tb2,
    const float* __restrict__ rw3, const float* __restrict__ rb3,
    const float* __restrict__ rg3, const float* __restrict__ rbb3,
    const float* __restrict__ sw3, const float* __restrict__ sb3,
    const float* __restrict__ tw3, const float* __restrict__ tb3)
{
    int gt  = blockIdx.x*blockDim.x + threadIdx.x;
    int NTH = gridDim.x*blockDim.x;

    for (int e=gt;e<15360;e+=NTH){
        int g=e/3072, r=e%3072, kt=r/1024, r2=r%1024, kk2=r2/32, q=r2%32, jp=q/8, tx=q%8;
        int oa=tx+16*jp, ob=oa+8, k0=2*kk2;
        float v0=0.f,v1=0.f,v2=0.f,v3=0.f;
        for (int c=0;c<64;c++){
            float s0 = sw1[(g*192+c)*64+k0]   + sw1[(g*192+64+c)*64+k0]   + sw1[(g*192+128+c)*64+k0];
            float s1 = sw1[(g*192+c)*64+k0+1] + sw1[(g*192+64+c)*64+k0+1] + sw1[(g*192+128+c)*64+k0+1];
            float wa = tw1[((g*64+oa)*64+c)*3+kt];
            float wb = tw1[((g*64+ob)*64+c)*3+kt];
            v0=fmaf(wa,s0,v0); v1=fmaf(wb,s0,v1); v2=fmaf(wa,s1,v2); v3=fmaf(wb,s1,v3);
        }
        g_tw1i[e]=make_float4(v0,v1,v2,v3);
    }
    for (int e=gt;e<15360;e+=NTH){
        int g=e/3072, r=e%3072, kt=r/1024, r2=r%1024, kk2=r2/32, q=r2%32, jp=q/8, tx=q%8;
        int oa=tx+16*jp, ob=oa+8, k0=2*kk2;
        g_tw3i[e]=make_float4(tw3[((g*64+oa)*64+k0)*3+kt],   tw3[((g*64+ob)*64+k0)*3+kt],
                              tw3[((g*64+oa)*64+k0+1)*3+kt], tw3[((g*64+ob)*64+k0+1)*3+kt]);
    }
    for (int e=gt;e<30720;e+=NTH){
        int g=e/6144, r=e%6144, kt=r/2048, r2=r%2048, kk2=r2/64, q=r2%64, jp=q/16, tx=q%16;
        int oa=tx+32*jp, ob=oa+16, k0=2*kk2;
        float v0=0.f,v1=0.f,v2=0.f,v3=0.f;
        for (int c=0;c<128;c++){
            float s0 = sw2[(g*384+c)*64+k0]   + sw2[(g*384+128+c)*64+k0]   + sw2[(g*384+256+c)*64+k0];
            float s1 = sw2[(g*384+c)*64+k0+1] + sw2[(g*384+128+c)*64+k0+1] + sw2[(g*384+256+c)*64+k0+1];
            float wa = tw2[((g*128+oa)*128+c)*3+kt];
            float wb = tw2[((g*128+ob)*128+c)*3+kt];
            v0=fmaf(wa,s0,v0); v1=fmaf(wb,s0,v1); v2=fmaf(wa,s1,v2); v3=fmaf(wb,s1,v3);
        }
        g_tw2i[e]=make_float4(v0,v1,v2,v3);
    }
    for (int e=gt;e<10240;e+=NTH){
        int g=e/2048, r=e%2048, kk2=r/32, q=r%32, jp=q/8, tx=q%8;
        int oa=tx+16*jp, ob=oa+8, k0=2*kk2;
        const float* w = sw3 + g*192*128;
        #define S3(o,c) (w[(o)*128+(c)] + w[(64+(o))*128+(c)] + w[(128+(o))*128+(c)])
        g_sw3i[e] = make_float4(S3(oa,k0), S3(ob,k0), S3(oa,k0+1), S3(ob,k0+1));
        #undef S3
    }
    for (int e=gt;e<10240;e+=NTH){
        int g=e/2048, r=e%2048, kk2=r/64, q=r%64, jp=q/16, tx=q%16;
        int oa=tx+32*jp, ob=oa+16, k0=2*kk2;
        const float* w = rw2 + g*8192;
        float sa_=rg2[g*128+oa]*BNS, sb_=rg2[g*128+ob]*BNS;
        g_rw2i[e] = make_float4(w[oa*64+k0]*sa_, w[ob*64+k0]*sb_, w[oa*64+k0+1]*sa_, w[ob*64+k0+1]*sb_);
    }
    for (int e=gt;e<10240;e+=NTH){
        int g=e/2048, r=e%2048, kk2=r/32, q=r%32, jp=q/8, tx=q%8;
        int oa=tx+16*jp, ob=oa+8, k0=2*kk2;
        const float* w = rw3 + g*8192;
        float sa_=rg3[g*64+oa]*BNS, sb_=rg3[g*64+ob]*BNS;
        g_rw3i[e] = make_float4(w[oa*128+k0]*sa_, w[ob*128+k0]*sb_, w[oa*128+k0+1]*sa_, w[ob*128+k0+1]*sb_);
    }
    for (int i=gt;i<5*64;i+=NTH){
        int g=i/64, o=i%64;
        float b0=0.f,b1=0.f,b2=0.f;
        for (int c=0;c<64;c++){
            float sb = sb1[g*192+c]+sb1[g*192+64+c]+sb1[g*192+128+c];
            b0=fmaf(tw1[((g*64+o)*64+c)*3+0],sb,b0);
            b1=fmaf(tw1[((g*64+o)*64+c)*3+1],sb,b1);
            b2=fmaf(tw1[((g*64+o)*64+c)*3+2],sb,b2);
        }
        g_cst1[i]=tb1[i]+b0+b1+b2;
        g_bb0_1[i]=b0; g_bb2_1[i]=b2;
        const float* s3=sb3+g*192;
        g_sb3[i]=s3[o]+s3[64+o]+s3[128+o];
        g_cst3[i]=tb3[i]+rb3[i]*rg3[i]*BNS+rbb3[i];
    }
    for (int i=gt;i<5*128;i+=NTH){
        int g=i/128, o=i%128;
        float b0=0.f,b1=0.f,b2=0.f;
        for (int c=0;c<128;c++){
            float sb = sb2[g*384+c]+sb2[g*384+128+c]+sb2[g*384+256+c];
            b0=fmaf(tw2[((g*128+o)*128+c)*3+0],sb,b0);
            b1=fmaf(tw2[((g*128+o)*128+c)*3+1],sb,b1);
            b2=fmaf(tw2[((g*128+o)*128+c)*3+2],sb,b2);
        }
        g_cst2[i]=tb2[i]+rb2[i]*rg2[i]*BNS+rbb2[i]+b0+b1+b2;
        g_bb0_2[i]=b0; g_bb2_2[i]=b2;
    }
    for (int i=gt;i<640;i+=NTH) g_zero[i]=0.f;
    if (gt==0){
        double fa[25][25];
        for (int i=0;i<25;i++) for (int j=0;j<25;j++) fa[i][j]=0.0;
        const int E[24][2]={{3,2},{2,20},{20,1},{1,0},{20,4},{4,5},{5,6},{6,22},
                            {6,7},{7,21},{20,8},{8,9},{9,10},{10,24},{10,11},{11,23},
                            {0,12},{12,13},{13,14},{14,15},{0,16},{16,17},{17,18},{18,19}};
        for (int k=0;k<24;k++){
            int i=E[k][0]-1, j=E[k][1]-1;
            fa[i][j]=1.0; fa[j][i]=1.0;
        }
        for (int i=0;i<25;i++) fa[i][i]+=1.0;
        for (int i=0;i<25;i++){
            double d=0; for (int j=0;j<25;j++) d+=fa[i][j];
            if (d==0.0) d=1.0;
            for (int j=0;j<25;j++) fa[i][j]/=d;
        }
        for (int g=0;g<5;g++){
            int n=c_gn[g];
            int js[6]; for (int u=0;u<n;u++) js[u]=c_s2j[c_gstart[g]+u];
            double sa[6][6];
            for (int u=0;u<n;u++) for (int v=0;v<n;v++) sa[u][v]=fa[js[u]][js[v]];
            for (int u=0;u<n;u++) sa[u][u]+=1.0;
            double dg[6];
            for (int u=0;u<n;u++){ double d=0; for (int v=0;v<n;v++) d+=sa[u][v]; dg[u]=d; }
            for (int node=1;node<n;node++)
                if (dg[node]==1.0){ sa[0][node]=1.0; sa[node][0]=1.0; }
            for (int u=0;u<6;u++) for (int v=0;v<6;v++){
                float val=0.f;
                if (u<n && v<n){
                    double d=0; for (int w=0;w<n;w++) d+=sa[u][w];
                    if (d==0.0) d=1.0;
                    val=(float)(sa[u][v]/d);
                }
                g_adj[g][u][v]=val;
            }
        }
    }
}

template<int CT,int NR>
__device__ __forceinline__ void gemm_kk4(unsigned long long (&acc)[NR][4],
                                         const float4* aPtr, int aStride,
                                         const ulonglong2* wPtr)
{
    float4 a[NR];
    #pragma unroll
    for (int i=0;i<NR;++i) a[i] = aPtr[aStride*i];
    #pragma unroll
    for (int h=0;h<2;++h){
        ulonglong2 w0 = wPtr[h*4*CT + 0*CT];
        ulonglong2 w1 = wPtr[h*4*CT + 1*CT];
        ulonglong2 w2 = wPtr[h*4*CT + 2*CT];
        ulonglong2 w3 = wPtr[h*4*CT + 3*CT];
        #pragma unroll
        for (int i=0;i<NR;++i){
            unsigned long long alo = bc2(h ? a[i].z : a[i].x);
            unsigned long long ahi = bc2(h ? a[i].w : a[i].y);
            ffma2(acc[i][0], alo, w0.x);
            ffma2(acc[i][1], alo, w1.x);
            ffma2(acc[i][2], alo, w2.x);
            ffma2(acc[i][3], alo, w3.x);
            ffma2(acc[i][0], ahi, w0.y);
            ffma2(acc[i][1], ahi, w1.y);
            ffma2(acc[i][2], ahi, w2.y);
            ffma2(acc[i][3], ahi, w3.y);
        }
    }
}

// Layer-3 GCN, N real slots per group (no padding work).
template<int N>
__global__ __launch_bounds__(256) void k_gcn3(const float* __restrict__ Y,
                                              float* __restrict__ Z,
                                              const float4* __restrict__ Wi,
                                              const float* __restrict__ Bv,
                                              int gbase)
{
    constexpr int CT = 8;
    constexpr int ROWS = 32*N;
    extern __shared__ float sm[];
    float4* sA4 = (float4*)sm;
    float4* sW4 = sA4 + ROWS*17;
    const ulonglong2* sWl = (const ulonglong2*)sW4;
    __shared__ float sAdj[6][6];

    const int g   = gbase + blockIdx.y;
    const int gs0 = c_gstart[g];
    const int bt0 = blockIdx.x * 32;
    const int tid = threadIdx.x;
    if (tid < 36) sAdj[tid/6][tid%6] = g_adj[g][tid/6][tid%6];

    const int ty = tid / CT, tx = tid % CT;
    unsigned long long acc[N][4];
    #pragma unroll
    for (int jp=0;jp<4;++jp){
        int oa = tx + 16*jp;
        unsigned long long b2 = pk2(Bv[g*64+oa], Bv[g*64+oa+8]);
        #pragma unroll
        for (int i=0;i<N;++i) acc[i][jp]=b2;
    }
    const float4* Wg = Wi + (size_t)g*2048;

    for (int ph=0; ph<2; ++ph){
        __syncthreads();
        for (int p=tid; p<32*16; p+=256){
            int c4l = p % 16, t = p / 16;
            int c4 = ph*16 + c4l;
            const float4* yp = (const float4*)(Y + ((size_t)(bt0+t)*25 + gs0)*128) + c4;
            float4 yv[N];
            #pragma unroll
            for (int vv=0; vv<N; ++vv) yv[vv] = yp[(size_t)vv*32];
            #pragma unroll
            for (int uu=0; uu<N; ++uu){
                float4 v = make_float4(0.f,0.f,0.f,0.f);
                #pragma unroll
                for (int vv=0; vv<N; ++vv){
                    float av = sAdj[uu][vv];
                    v.x += av*yv[vv].x; v.y += av*yv[vv].y;
                    v.z += av*yv[vv].z; v.w += av*yv[vv].w;
                }
                sA4[(t*N+uu)*17 + c4l] = v;
            }
        }
        for (int p=tid; p<1024; p+=256) sW4[p] = Wg[ph*1024 + p];
        __syncthreads();
        #pragma unroll 8
        for (int kk4l=0;kk4l<16;++kk4l)
            gemm_kk4<CT,N>(acc, sA4 + ty*17 + kk4l, 32*17, sWl + 2*kk4l*4*CT + tx);
    }

    #pragma unroll
    for (int i=0;i<N;++i){
        int r = ty+32*i, t = r/N, u = r%N;
        float* zp = Z + ((size_t)(bt0+t)*25 + gs0+u)*64;
        #pragma unroll
        for (int jp=0;jp<4;++jp){
            float lo,hi; unpk(acc[i][jp], lo, hi);
            int oa = tx + 16*jp;
            zp[oa] = lo; zp[oa+8] = hi;
        }
    }
}

// tconv, N real slots; TBL=16; per-kt W staging; GCONV/EMB staging gathers once per (hb,c4).
template<int COUT,int CRES,int MODE,int GCONV,int EMB,int N>
__global__ __launch_bounds__((COUT/8)*16)
void k_tconv(const float* __restrict__ Zin, const float* __restrict__ Yres,
             float* __restrict__ Yout,
             const float4* __restrict__ TWi, const float4* __restrict__ RWi,
             const float* __restrict__ CST, const float* __restrict__ BB0,
             const float* __restrict__ BB2,
             const float* __restrict__ GS, const float* __restrict__ BB,
             const float* __restrict__ EW, const float* __restrict__ EB,
             int gbase)
{
    constexpr int CT  = COUT/8;
    constexpr int TH  = CT*16;
    constexpr int C4  = 16;
    constexpr int PRZ = 17;
    constexpr int TBL = 16;
    constexpr int WKT = 32*4*CT;
    constexpr int SBUF4 = (TBL+2)*N*PRZ;
    extern __shared__ float sm[];
    float4* sB4 = (float4*)sm;
    float4* sW4 = sB4 + SBUF4;
    const ulonglong2* sWl = (const ulonglong2*)sW4;
    float* sX  = (float*)(sW4 + WKT);       // [(TBL+2)*N*3] (EMB only)
    float* sEW = sX + (TBL+2)*N*3;          // [192]
    float* sEB = sEW + 192;                 // [64]
    __shared__ float sAdj[6][6];

    const int g   = gbase + blockIdx.y;
    const int gs0 = c_gstart[g];
    const int bt0 = blockIdx.x * TBL;
    const int t0  = bt0 & (NT-1);
    const int tid = threadIdx.x, ty = tid/CT, tx = tid%CT;

    if (GCONV){
        if (tid < 36) sAdj[tid/6][tid%6] = g_adj[g][tid/6][tid%6];
    }
    if (EMB){
        for (int p=tid; p<192; p+=TH) sEW[p] = EW[p];
        for (int p=tid; p<64;  p+=TH) sEB[p] = EB[p];
        for (int p=tid; p<(TBL+2)*N; p+=TH){
            int u = p % N, hb = p / N;
            int t = t0 + hb - 1;
            float x0=0.f,x1=0.f,x2=0.f;
            if (t >= 0 && t < NT){
                int j = c_s2j[gs0+u];
                const float* xp = Zin + ((size_t)(bt0+hb-1)*25 + j)*3;
                x0=xp[0]; x1=xp[1]; x2=xp[2];
            }
            sX[p*3+0]=x0; sX[p*3+1]=x1; sX[p*3+2]=x2;
        }
    }
    if (GCONV || EMB) __syncthreads();

    if (EMB){
        for (int p=tid; p<(TBL+2)*C4; p+=TH){
            int c4 = p % C4, hb = p / C4;
            int t = t0 + hb - 1;
            bool valid = (t >= 0 && t < NT);
            float h[N][4];
            if (valid){
                #pragma unroll
                for (int vv=0; vv<N; ++vv){
                    const float* xr = sX + (hb*N+vv)*3;
                    float x0=xr[0], x1=xr[1], x2=xr[2];
                    #pragma unroll
                    for (int cc=0;cc<4;++cc){
                        int c = c4*4+cc;
                        h[vv][cc] = fmaf(x2, sEW[c*3+2],
                                    fmaf(x1, sEW[c*3+1],
                                    fmaf(x0, sEW[c*3+0], sEB[c])));
                    }
                }
            }
            #pragma unroll
            for (int uu=0; uu<N; ++uu){
                float4 v = make_float4(0.f,0.f,0.f,0.f);
                if (valid){
                    #pragma unroll
                    for (int vv=0; vv<N; ++vv){
                        float av = sAdj[uu][vv];
                        v.x = fmaf(av,h[vv][0],v.x);
                        v.y = fmaf(av,h[vv][1],v.y);
                        v.z = fmaf(av,h[vv][2],v.z);
                        v.w = fmaf(av,h[vv][3],v.w);
                    }
                }
                sB4[(hb*N+uu)*PRZ + c4] = v;
            }
        }
    } else if (GCONV){
        for (int p=tid; p<(TBL+2)*C4; p+=TH){
            int c4 = p % C4, hb = p / C4;
            int t = t0 + hb - 1;
            bool valid = (t >= 0 && t < NT);
            float4 yv[N];
            if (valid){
                const float4* yp = (const float4*)(Zin + ((size_t)(bt0+hb-1)*25 + gs0)*64) + c4;
                #pragma unroll
                for (int vv=0; vv<N; ++vv) yv[vv] = yp[(size_t)vv*C4];
            }
            #pragma unroll
            for (int uu=0; uu<N; ++uu){
                float4 v = make_float4(0.f,0.f,0.f,0.f);
                if (valid){
                    #pragma unroll
                    for (int vv=0; vv<N; ++vv){
                        float av = sAdj[uu][vv];
                        v.x += av*yv[vv].x; v.y += av*yv[vv].y;
                        v.z += av*yv[vv].z; v.w += av*yv[vv].w;
                    }
                }
                sB4[(hb*N+uu)*PRZ + c4] = v;
            }
        }
    } else {
        for (int p=tid; p<(TBL+2)*N*C4; p+=TH){
            int c4 = p % C4, r = p / C4, uu = r % N, hb = r / N;
            int t = t0 + hb - 1;
            float4 v = make_float4(0.f,0.f,0.f,0.f);
            if (t >= 0 && t < NT)
                v = ((const float4*)(Zin + ((size_t)(bt0+hb-1)*25 + gs0+uu)*64))[c4];
            sB4[r*PRZ + c4] = v;
        }
    }

    unsigned long long acc[N][4];
    unsigned long long z2 = pk2(0.f, 0.f);
    #pragma unroll
    for (int i=0;i<N;++i)
        #pragma unroll
        for (int jp=0;jp<4;++jp) acc[i][jp]=z2;

    const float4* TWg = TWi + (size_t)g*3*WKT;
    for (int kt=0;kt<3;++kt){
        __syncthreads();
        for (int p=tid; p<WKT; p+=TH) sW4[p] = TWg[kt*WKT + p];
        __syncthreads();
        #pragma unroll 8
        for (int kk4=0;kk4<C4;++kk4)
            gemm_kk4<CT,N>(acc, sB4 + (ty + N*kt)*PRZ + kk4, 16*PRZ,
                           sWl + 2*kk4*4*CT + tx);
    }

    if (MODE==1){
        constexpr int RPASS = CRES/64;
        constexpr int RWP   = 32*4*CT;
        const float4* RWg = RWi + (size_t)g*2048;
        for (int ph=0; ph<RPASS; ++ph){
            __syncthreads();
            for (int p=tid; p<TBL*N*16; p+=TH){
                int c4l = p % 16, r = p / 16, uu = r % N, t = r / N;
                float4 v = ((const float4*)(Yres + ((size_t)(bt0+t)*25 + gs0+uu)*CRES))[ph*16 + c4l];
                sB4[r*PRZ + c4l] = v;
            }
            for (int p=tid; p<RWP; p+=TH) sW4[p] = RWg[ph*RWP + p];
            __syncthreads();
            #pragma unroll 8
            for (int kk4l=0;kk4l<16;++kk4l)
                gemm_kk4<CT,N>(acc, sB4 + ty*PRZ + kk4l, 16*PRZ, sWl + 2*kk4l*4*CT + tx);
        }
    }

    float cst[8], gsv[8], bbv[8];
    #pragma unroll
    for (int jp=0;jp<4;++jp){
        int oa = tx + CT*2*jp;
        cst[2*jp]   = CST[g*COUT+oa];       cst[2*jp+1] = CST[g*COUT+oa+CT];
        gsv[2*jp]   = GS [g*COUT+oa]*BNS;   gsv[2*jp+1] = GS [g*COUT+oa+CT]*BNS;
        bbv[2*jp]   = BB [g*COUT+oa];       bbv[2*jp+1] = BB [g*COUT+oa+CT];
    }
    #pragma unroll
    for (int i=0;i<N;++i){
        int r = ty+16*i, t = r/N, u = r%N;
        size_t base = ((size_t)(bt0+t)*25 + gs0+u)*COUT;
        int tg = t0 + t;
        bool e0 = (tg==0), e2 = (tg==NT-1);
        const float* xr = EMB ? (sX + ((t+1)*N+u)*3) : (const float*)0;
        float x0=0.f,x1=0.f,x2=0.f;
        if (EMB){ x0=xr[0]; x1=xr[1]; x2=xr[2]; }
        #pragma unroll
        for (int jp=0;jp<4;++jp){
            float lo,hi; unpk(acc[i][jp], lo, hi);
            int oa = tx + CT*2*jp;
            int ob = oa + CT;
            float pa = lo + cst[2*jp];
            float pb = hi + cst[2*jp+1];
            if (e0){ pa -= BB0[g*COUT+oa]; pb -= BB0[g*COUT+ob]; }
            if (e2){ pa -= BB2[g*COUT+oa]; pb -= BB2[g*COUT+ob]; }
            if (MODE==0){
                if (EMB){
                    pa += fmaf(x2,sEW[oa*3+2], fmaf(x1,sEW[oa*3+1], fmaf(x0,sEW[oa*3+0], sEB[oa])));
                    pb += fmaf(x2,sEW[ob*3+2], fmaf(x1,sEW[ob*3+1], fmaf(x0,sEW[ob*3+0], sEB[ob])));
                } else {
                    pa += Yres[base+oa]; pb += Yres[base+ob];
                }
            }
            Yout[base+oa] = fmaxf(pa*gsv[2*jp]   + bbv[2*jp],   0.f);
            Yout[base+ob] = fmaxf(pb*gsv[2*jp+1] + bbv[2*jp+1], 0.f);
        }
    }
}

__global__ __launch_bounds__(256) void k_featvq(const float* __restrict__ cb,
                                                float* __restrict__ out)
{
    int g = blockIdx.x, b = blockIdx.y;
    int tid = threadIdx.x;
    int o = tid & 63, part = tid >> 6;
    int n = c_gn[g], gs0 = c_gstart[g];
    float s = 0.f;
    int total = NT*n;
    for (int q=part; q<total; q+=4){
        int t = q / n, u = q % n;
        s += g_Y3[((size_t)(b*NT+t)*25 + gs0+u)*64 + o];
    }
    __shared__ float red[256];
    __shared__ float f[64];
    red[tid]=s; __syncthreads();
    if (part==0)
        f[o] = (red[o]+red[64+o]+red[128+o]+red[192+o]) / (float)(NT*n);
    __syncthreads();

    __shared__ float ds[128];
    __shared__ int   sidx;
    if (tid < 128){
        const float* ck = cb + (g*128 + tid)*64;
        float dot=0.f, scb=0.f;
        for (int oo=0;oo<64;++oo){ dot += f[oo]*ck[oo]; scb += ck[oo]*ck[oo]; }
        ds[tid] = scb - 2.f*dot;
    }
    __syncthreads();
    if (tid==0){
        float best = ds[0]; int bi = 0;
        for (int kk=1;kk<128;++kk) if (ds[kk] < best){ best = ds[kk]; bi = kk; }
        sidx = bi;
    }
    __syncthreads();
    int idx = sidx;
    __shared__ float dsq[64];
    if (tid < 64){
        float q = cb[(g*128 + idx)*64 + tid];
        out[(g*64+b)*64 + tid] = q;
        float dd = q - f[tid];
        dsq[tid] = dd*dd;
    }
    __syncthreads();
    if (tid==0){
        float ss=0.f;
        for (int oo=0;oo<64;++oo) ss += dsq[oo];
        g_loss[g*64+b] = 1.25f * ss / 4096.f;
        out[5*64*64 + 1 + g*64 + b] = (float)idx;
    }
}

__global__ void k_lred(float* out){
    __shared__ float s[320];
    int t = threadIdx.x;
    if (t < 320) s[t] = g_loss[t];
    __syncthreads();
    if (t==0){
        float a=0.f;
        for (int i=0;i<320;i++) a += s[i];
        out[5*64*64] = a;
    }
}

extern "C" void kernel_launch(void* const* d_in, const int* in_sizes, int n_in,
                              void* d_out, int out_size)
{
    const float* x        = (const float*)d_in[0];
    const float* embed_w  = (const float*)d_in[1];
    const float* embed_b  = (const float*)d_in[2];
    const float* sgcn_w1  = (const float*)d_in[3];
    const float* sgcn_b1  = (const float*)d_in[4];
    const float* tconv_w1 = (const float*)d_in[5];
    const float* tconv_b1 = (const float*)d_in[6];
    const float* bn_g1    = (const float*)d_in[7];
    const float* bn_b1    = (const float*)d_in[8];
    const float* res_w2   = (const float*)d_in[9];
    const float* res_b2   = (const float*)d_in[10];
    const float* resbn_g2 = (const float*)d_in[11];
    const float* resbn_b2 = (const float*)d_in[12];
    const float* sgcn_w2  = (const float*)d_in[13];
    const float* sgcn_b2  = (const float*)d_in[14];
    const float* tconv_w2 = (const float*)d_in[15];
    const float* tconv_b2 = (const float*)d_in[16];
    const float* bn_g2    = (const float*)d_in[17];
    const float* bn_b2    = (const float*)d_in[18];
    const float* res_w3   = (const float*)d_in[19];
    const float* res_b3   = (const float*)d_in[20];
    const float* resbn_g3 = (const float*)d_in[21];
    const float* resbn_b3 = (const float*)d_in[22];
    const float* sgcn_w3  = (const float*)d_in[23];
    const float* sgcn_b3  = (const float*)d_in[24];
    const float* tconv_w3 = (const float*)d_in[25];
    const float* tconv_b3 = (const float*)d_in[26];
    const float* bn_g3    = (const float*)d_in[27];
    const float* bn_b3    = (const float*)d_in[28];
    const float* codebooks= (const float*)d_in[29];
    float* out = (float*)d_out;

    void *vp;
    #define SYM(name, s, T) cudaGetSymbolAddress(&vp, s); T* name = (T*)vp;
    SYM(pZ, g_Z, float)  SYM(pY1, g_Y1, float)
    SYM(pY2, g_Y2, float)  SYM(pY3, g_Y3, float)
    SYM(pSB3,g_sb3,float)
    SYM(pC1, g_cst1,float) SYM(pB01,g_bb0_1,float) SYM(pB21,g_bb2_1,float)
    SYM(pC2, g_cst2,float) SYM(pB02,g_bb0_2,float) SYM(pB22,g_bb2_2,float)
    SYM(pC3, g_cst3,float) SYM(pZERO,g_zero,float)
    SYM(pSW3,g_sw3i,float4)
    SYM(pRW2,g_rw2i,float4) SYM(pRW3,g_rw3i,float4)
    SYM(pTW1,g_tw1i,float4) SYM(pTW2,g_tw2i,float4) SYM(pTW3,g_tw3i,float4)
    #undef SYM

    dim3 g16_1(BT/16, 1), g16_2(BT/16, 2);
    dim3 g32_1(BT/32, 1), g32_2(BT/32, 2);

    auto smt = [](int N, int wkt, int emb){
        return (size_t)(18*N*17 + wkt)*16 + (emb ? (18*N*3 + 192 + 64)*4 : 0);
    };
    auto smg = [](int N){ return (size_t)(32*N*17 + 1024)*16; };

    #define SETSM(K, B) cudaFuncSetAttribute((K), cudaFuncAttributeMaxDynamicSharedMemorySize, (int)(B))
    SETSM((k_tconv<64,64,0,1,1,5>),  smt(5,1024,1));
    SETSM((k_tconv<64,64,0,1,1,6>),  smt(6,1024,1));
    SETSM((k_tconv<64,64,0,1,1,4>),  smt(4,1024,1));
    SETSM((k_tconv<128,64,1,1,0,5>), smt(5,2048,0));
    SETSM((k_tconv<128,64,1,1,0,6>), smt(6,2048,0));
    SETSM((k_tconv<128,64,1,1,0,4>), smt(4,2048,0));
    SETSM((k_gcn3<5>), smg(5));
    SETSM((k_gcn3<6>), smg(6));
    SETSM((k_gcn3<4>), smg(4));
    SETSM((k_tconv<64,128,1,0,0,5>), smt(5,1024,0));
    SETSM((k_tconv<64,128,1,0,0,6>), smt(6,1024,0));
    SETSM((k_tconv<64,128,1,0,0,4>), smt(4,1024,0));
    #undef SETSM

    k_prep<<<64,256>>>(sgcn_w1, sgcn_b1, tconv_w1, tconv_b1,
                       res_w2, res_b2, resbn_g2, resbn_b2, sgcn_w2, sgcn_b2, tconv_w2, tconv_b2,
                       res_w3, res_b3, resbn_g3, resbn_b3, sgcn_w3, sgcn_b3, tconv_w3, tconv_b3);

    // Layer 1 (embed+graph+tconv fused)
    k_tconv<64,64,0,1,1,5><<<g16_1,128,smt(5,1024,1)>>>(x, x, pY1, pTW1, pRW2, pC1, pB01, pB21, bn_g1, bn_b1, embed_w, embed_b, 0);
    k_tconv<64,64,0,1,1,6><<<g16_2,128,smt(6,1024,1)>>>(x, x, pY1, pTW1, pRW2, pC1, pB01, pB21, bn_g1, bn_b1, embed_w, embed_b, 1);
    k_tconv<64,64,0,1,1,4><<<g16_2,128,smt(4,1024,1)>>>(x, x, pY1, pTW1, pRW2, pC1, pB01, pB21, bn_g1, bn_b1, embed_w, embed_b, 3);
    // Layer 2
    k_tconv<128,64,1,1,0,5><<<g16_1,256,smt(5,2048,0)>>>(pY1, pY1, pY2, pTW2, pRW2, pC2, pB02, pB22, bn_g2, bn_b2, nullptr, nullptr, 0);
    k_tconv<128,64,1,1,0,6><<<g16_2,256,smt(6,2048,0)>>>(pY1, pY1, pY2, pTW2, pRW2, pC2, pB02, pB22, bn_g2, bn_b2, nullptr, nullptr, 1);
    k_tconv<128,64,1,1,0,4><<<g16_2,256,smt(4,2048,0)>>>(pY1, pY1, pY2, pTW2, pRW2, pC2, pB02, pB22, bn_g2, bn_b2, nullptr, nullptr, 3);
    // Layer 3
    k_gcn3<5><<<g32_1,256,smg(5)>>>(pY2, pZ, pSW3, pSB3, 0);
    k_gcn3<6><<<g32_2,256,smg(6)>>>(pY2, pZ, pSW3, pSB3, 1);
    k_gcn3<4><<<g32_2,256,smg(4)>>>(pY2, pZ, pSW3, pSB3, 3);
    k_tconv<64,128,1,0,0,5><<<g16_1,128,smt(5,1024,0)>>>(pZ, pY2, pY3, pTW3, pRW3, pC3, pZERO, pZERO, bn_g3, bn_b3, nullptr, nullptr, 0);
    k_tconv<64,128,1,0,0,6><<<g16_2,128,smt(6,1024,0)>>>(pZ, pY2, pY3, pTW3, pRW3, pC3, pZERO, pZERO, bn_g3, bn_b3, nullptr, nullptr, 1);
    k_tconv<64,128,1,0,0,4><<<g16_2,128,smt(4,1024,0)>>>(pZ, pY2, pY3, pTW3, pRW3, pC3, pZERO, pZERO, bn_g3, bn_b3, nullptr, nullptr, 3);

    k_featvq<<<dim3(5,64),256>>>(codebooks, out);
    k_lred<<<1,512>>>(out);
}

// round 15
// speedup vs baseline: 1.3051x; 1.0452x over previous
#include <cuda_runtime.h>

#define NB 64
#define NT 256
#define BT (NB*NT)
#define BNS 0.9999950000374997f

__constant__ int c_s2j[25] = {0,1,2,3,20, 4,5,6,7,21,22, 8,9,10,11,23,24, 12,13,14,15, 16,17,18,19};
__constant__ int c_gstart[5] = {0,5,11,17,21};
__constant__ int c_gn[5]     = {5,6,6,4,4};

__device__ float g_adj[5][6][6];
__device__ float g_Z [BT*25*64];
__device__ float g_Y1[BT*25*64];
__device__ float g_Y2[BT*25*128];
__device__ float g_Y3[BT*25*64];
__device__ float g_loss[5*64];
__device__ float g_sb3[5*64];
__device__ float g_cst1[5*64],  g_bb0_1[5*64],  g_bb2_1[5*64];
__device__ float g_cst2[5*128], g_bb0_2[5*128], g_bb2_2[5*128];
__device__ float g_cst3[5*64];
__device__ float g_zero[640];
__device__ float4 g_sw3i[10240];
__device__ float4 g_rw2i[10240];
__device__ float4 g_rw3i[10240];
__device__ float4 g_tw1i[15360];
__device__ float4 g_tw2i[30720];
__device__ float4 g_tw3i[15360];

__device__ __forceinline__ unsigned long long bc2(float x){
    unsigned long long r; unsigned u = __float_as_uint(x);
    asm("mov.b64 %0, {%1, %1};" : "=l"(r) : "r"(u));
    return r;
}
__device__ __forceinline__ unsigned long long pk2(float a, float b){
    unsigned long long r;
    asm("mov.b64 %0, {%1, %2};" : "=l"(r) : "r"(__float_as_uint(a)), "r"(__float_as_uint(b)));
    return r;
}
__device__ __forceinline__ void ffma2(unsigned long long& c, unsigned long long a, unsigned long long b){
    asm("fma.rn.f32x2 %0, %1, %2, %0;" : "+l"(c) : "l"(a), "l"(b));
}
__device__ __forceinline__ void unpk(unsigned long long v, float& lo, float& hi){
    unsigned a,b; asm("mov.b64 {%0, %1}, %2;" : "=r"(a), "=r"(b) : "l"(v));
    lo = __uint_as_float(a); hi = __uint_as_float(b);
}

__global__ __launch_bounds__(256) void k_prep(
    const float* __restrict__ sw1, const float* __restrict__ sb1,
    const float* __restrict__ tw1, const float* __restrict__ tb1,
    const float* __restrict__ rw2, const float* __restrict__ rb2,
    const float* __restrict__ rg2, const float* __restrict__ rbb2,
    const float* __restrict__ sw2, const float* __restrict__ sb2,
    const float* __restrict__ tw2, const float* __restrict__ tb2,
    const float* __restrict__ rw3, const float* __restrict__ rb3,
    const float* __restrict__ rg3, const float* __restrict__ rbb3,
    const float* __restrict__ sw3, const float* __restrict__ sb3,
    const float* __restrict__ tw3, const float* __restrict__ tb3)
{
    int gt  = blockIdx.x*blockDim.x + threadIdx.x;
    int NTH = gridDim.x*blockDim.x;

    for (int e=gt;e<15360;e+=NTH){
        int g=e/3072, r=e%3072, kt=r/1024, r2=r%1024, kk2=r2/32, q=r2%32, jp=q/8, tx=q%8;
        int oa=tx+16*jp, ob=oa+8, k0=2*kk2;
        float v0=0.f,v1=0.f,v2=0.f,v3=0.f;
        for (int c=0;c<64;c++){
            float s0 = sw1[(g*192+c)*64+k0]   + sw1[(g*192+64+c)*64+k0]   + sw1[(g*192+128+c)*64+k0];
            float s1 = sw1[(g*192+c)*64+k0+1] + sw1[(g*192+64+c)*64+k0+1] + sw1[(g*192+128+c)*64+k0+1];
            float wa = tw1[((g*64+oa)*64+c)*3+kt];
            float wb = tw1[((g*64+ob)*64+c)*3+kt];
            v0=fmaf(wa,s0,v0); v1=fmaf(wb,s0,v1); v2=fmaf(wa,s1,v2); v3=fmaf(wb,s1,v3);
        }
        g_tw1i[e]=make_float4(v0,v1,v2,v3);
    }
    for (int e=gt;e<15360;e+=NTH){
        int g=e/3072, r=e%3072, kt=r/1024, r2=r%1024, kk2=r2/32, q=r2%32, jp=q/8, tx=q%8;
        int oa=tx+16*jp, ob=oa+8, k0=2*kk2;
        g_tw3i[e]=make_float4(tw3[((g*64+oa)*64+k0)*3+kt],   tw3[((g*64+ob)*64+k0)*3+kt],
                              tw3[((g*64+oa)*64+k0+1)*3+kt], tw3[((g*64+ob)*64+k0+1)*3+kt]);
    }
    for (int e=gt;e<30720;e+=NTH){
        int g=e/6144, r=e%6144, kt=r/2048, r2=r%2048, kk2=r2/64, q=r2%64, jp=q/16, tx=q%16;
        int oa=tx+32*jp, ob=oa+16, k0=2*kk2;
        float v0=0.f,v1=0.f,v2=0.f,v3=0.f;
        for (int c=0;c<128;c++){
            float s0 = sw2[(g*384+c)*64+k0]   + sw2[(g*384+128+c)*64+k0]   + sw2[(g*384+256+c)*64+k0];
            float s1 = sw2[(g*384+c)*64+k0+1] + sw2[(g*384+128+c)*64+k0+1] + sw2[(g*384+256+c)*64+k0+1];
            float wa = tw2[((g*128+oa)*128+c)*3+kt];
            float wb = tw2[((g*128+ob)*128+c)*3+kt];
            v0=fmaf(wa,s0,v0); v1=fmaf(wb,s0,v1); v2=fmaf(wa,s1,v2); v3=fmaf(wb,s1,v3);
        }
        g_tw2i[e]=make_float4(v0,v1,v2,v3);
    }
    for (int e=gt;e<10240;e+=NTH){
        int g=e/2048, r=e%2048, kk2=r/32, q=r%32, jp=q/8, tx=q%8;
        int oa=tx+16*jp, ob=oa+8, k0=2*kk2;
        const float* w = sw3 + g*192*128;
        #define S3(o,c) (w[(o)*128+(c)] + w[(64+(o))*128+(c)] + w[(128+(o))*128+(c)])
        g_sw3i[e] = make_float4(S3(oa,k0), S3(ob,k0), S3(oa,k0+1), S3(ob,k0+1));
        #undef S3
    }
    for (int e=gt;e<10240;e+=NTH){
        int g=e/2048, r=e%2048, kk2=r/64, q=r%64, jp=q/16, tx=q%16;
        int oa=tx+32*jp, ob=oa+16, k0=2*kk2;
        const float* w = rw2 + g*8192;
        float sa_=rg2[g*128+oa]*BNS, sb_=rg2[g*128+ob]*BNS;
        g_rw2i[e] = make_float4(w[oa*64+k0]*sa_, w[ob*64+k0]*sb_, w[oa*64+k0+1]*sa_, w[ob*64+k0+1]*sb_);
    }
    for (int e=gt;e<10240;e+=NTH){
        int g=e/2048, r=e%2048, kk2=r/32, q=r%32, jp=q/8, tx=q%8;
        int oa=tx+16*jp, ob=oa+8, k0=2*kk2;
        const float* w = rw3 + g*8192;
        float sa_=rg3[g*64+oa]*BNS, sb_=rg3[g*64+ob]*BNS;
        g_rw3i[e] = make_float4(w[oa*128+k0]*sa_, w[ob*128+k0]*sb_, w[oa*128+k0+1]*sa_, w[ob*128+k0+1]*sb_);
    }
    for (int i=gt;i<5*64;i+=NTH){
        int g=i/64, o=i%64;
        float b0=0.f,b1=0.f,b2=0.f;
        for (int c=0;c<64;c++){
            float sb = sb1[g*192+c]+sb1[g*192+64+c]+sb1[g*192+128+c];
            b0=fmaf(tw1[((g*64+o)*64+c)*3+0],sb,b0);
            b1=fmaf(tw1[((g*64+o)*64+c)*3+1],sb,b1);
            b2=fmaf(tw1[((g*64+o)*64+c)*3+2],sb,b2);
        }
        g_cst1[i]=tb1[i]+b0+b1+b2;
        g_bb0_1[i]=b0; g_bb2_1[i]=b2;
        const float* s3=sb3+g*192;
        g_sb3[i]=s3[o]+s3[64+o]+s3[128+o];
        g_cst3[i]=tb3[i]+rb3[i]*rg3[i]*BNS+rbb3[i];
    }
    for (int i=gt;i<5*128;i+=NTH){
        int g=i/128, o=i%128;
        float b0=0.f,b1=0.f,b2=0.f;
        for (int c=0;c<128;c++){
            float sb = sb2[g*384+c]+sb2[g*384+128+c]+sb2[g*384+256+c];
            b0=fmaf(tw2[((g*128+o)*128+c)*3+0],sb,b0);
            b1=fmaf(tw2[((g*128+o)*128+c)*3+1],sb,b1);
            b2=fmaf(tw2[((g*128+o)*128+c)*3+2],sb,b2);
        }
        g_cst2[i]=tb2[i]+rb2[i]*rg2[i]*BNS+rbb2[i]+b0+b1+b2;
        g_bb0_2[i]=b0; g_bb2_2[i]=b2;
    }
    for (int i=gt;i<640;i+=NTH) g_zero[i]=0.f;
    if (gt==0){
        double fa[25][25];
        for (int i=0;i<25;i++) for (int j=0;j<25;j++) fa[i][j]=0.0;
        const int E[24][2]={{3,2},{2,20},{20,1},{1,0},{20,4},{4,5},{5,6},{6,22},
                            {6,7},{7,21},{20,8},{8,9},{9,10},{10,24},{10,11},{11,23},
                            {0,12},{12,13},{13,14},{14,15},{0,16},{16,17},{17,18},{18,19}};
        for (int k=0;k<24;k++){
            int i=E[k][0]-1, j=E[k][1]-1;
            fa[i][j]=1.0; fa[j][i]=1.0;
        }
        for (int i=0;i<25;i++) fa[i][i]+=1.0;
        for (int i=0;i<25;i++){
            double d=0; for (int j=0;j<25;j++) d+=fa[i][j];
            if (d==0.0) d=1.0;
            for (int j=0;j<25;j++) fa[i][j]/=d;
        }
        for (int g=0;g<5;g++){
            int n=c_gn[g];
            int js[6]; for (int u=0;u<n;u++) js[u]=c_s2j[c_gstart[g]+u];
            double sa[6][6];
            for (int u=0;u<n;u++) for (int v=0;v<n;v++) sa[u][v]=fa[js[u]][js[v]];
            for (int u=0;u<n;u++) sa[u][u]+=1.0;
            double dg[6];
            for (int u=0;u<n;u++){ double d=0; for (int v=0;v<n;v++) d+=sa[u][v]; dg[u]=d; }
            for (int node=1;node<n;node++)
                if (dg[node]==1.0){ sa[0][node]=1.0; sa[node][0]=1.0; }
            for (int u=0;u<6;u++) for (int v=0;v<6;v++){
                float val=0.f;
                if (u<n && v<n){
                    double d=0; for (int w=0;w<n;w++) d+=sa[u][w];
                    if (d==0.0) d=1.0;
                    val=(float)(sa[u][v]/d);
                }
                g_adj[g][u][v]=val;
            }
        }
    }
}

template<int CT,int NR>
__device__ __forceinline__ void gemm_kk4(unsigned long long (&acc)[NR][4],
                                         const float4* aPtr, int aStride,
                                         const ulonglong2* wPtr)
{
    float4 a[NR];
    #pragma unroll
    for (int i=0;i<NR;++i) a[i] = aPtr[aStride*i];
    #pragma unroll
    for (int h=0;h<2;++h){
        ulonglong2 w0 = wPtr[h*4*CT + 0*CT];
        ulonglong2 w1 = wPtr[h*4*CT + 1*CT];
        ulonglong2 w2 = wPtr[h*4*CT + 2*CT];
        ulonglong2 w3 = wPtr[h*4*CT + 3*CT];
        #pragma unroll
        for (int i=0;i<NR;++i){
            unsigned long long alo = bc2(h ? a[i].z : a[i].x);
            unsigned long long ahi = bc2(h ? a[i].w : a[i].y);
            ffma2(acc[i][0], alo, w0.x);
            ffma2(acc[i][1], alo, w1.x);
            ffma2(acc[i][2], alo, w2.x);
            ffma2(acc[i][3], alo, w3.x);
            ffma2(acc[i][0], ahi, w0.y);
            ffma2(acc[i][1], ahi, w1.y);
            ffma2(acc[i][2], ahi, w2.y);
            ffma2(acc[i][3], ahi, w3.y);
        }
    }
}

// ---- Layer-3 GCN body (N real slots), dispatched per group ----
template<int N>
__device__ __forceinline__ void gcn3_body(const float* __restrict__ Y,
                                          float* __restrict__ Z,
                                          const float4* __restrict__ Wi,
                                          const float* __restrict__ Bv,
                                          int g, float* sm)
{
    constexpr int CT = 8;
    float4* sA4 = (float4*)sm;
    float4* sW4 = sA4 + 32*N*17;
    const ulonglong2* sWl = (const ulonglong2*)sW4;
    __shared__ float sAdj[6][6];

    const int gs0 = c_gstart[g];
    const int bt0 = blockIdx.x * 32;
    const int tid = threadIdx.x;
    if (tid < 36) sAdj[tid/6][tid%6] = g_adj[g][tid/6][tid%6];

    const int ty = tid / CT, tx = tid % CT;
    unsigned long long acc[N][4];
    #pragma unroll
    for (int jp=0;jp<4;++jp){
        int oa = tx + 16*jp;
        unsigned long long b2 = pk2(Bv[g*64+oa], Bv[g*64+oa+8]);
        #pragma unroll
        for (int i=0;i<N;++i) acc[i][jp]=b2;
    }
    const float4* Wg = Wi + (size_t)g*2048;

    for (int ph=0; ph<2; ++ph){
        __syncthreads();
        for (int p=tid; p<32*16; p+=256){
            int c4l = p % 16, t = p / 16;
            int c4 = ph*16 + c4l;
            const float4* yp = (const float4*)(Y + ((size_t)(bt0+t)*25 + gs0)*128) + c4;
            float4 yv[N];
            #pragma unroll
            for (int vv=0; vv<N; ++vv) yv[vv] = yp[(size_t)vv*32];
            #pragma unroll
            for (int uu=0; uu<N; ++uu){
                float4 v = make_float4(0.f,0.f,0.f,0.f);
                #pragma unroll
                for (int vv=0; vv<N; ++vv){
                    float av = sAdj[uu][vv];
                    v.x += av*yv[vv].x; v.y += av*yv[vv].y;
                    v.z += av*yv[vv].z; v.w += av*yv[vv].w;
                }
                sA4[(t*N+uu)*17 + c4l] = v;
            }
        }
        for (int p=tid; p<1024; p+=256) sW4[p] = Wg[ph*1024 + p];
        __syncthreads();
        #pragma unroll 8
        for (int kk4l=0;kk4l<16;++kk4l)
            gemm_kk4<CT,N>(acc, sA4 + ty*17 + kk4l, 32*17, sWl + 2*kk4l*4*CT + tx);
    }

    #pragma unroll
    for (int i=0;i<N;++i){
        int r = ty+32*i, t = r/N, u = r%N;
        float* zp = Z + ((size_t)(bt0+t)*25 + gs0+u)*64;
        #pragma unroll
        for (int jp=0;jp<4;++jp){
            float lo,hi; unpk(acc[i][jp], lo, hi);
            int oa = tx + 16*jp;
            zp[oa] = lo; zp[oa+8] = hi;
        }
    }
}

__global__ __launch_bounds__(256) void k_gcn3(const float* __restrict__ Y,
                                              float* __restrict__ Z,
                                              const float4* __restrict__ Wi,
                                              const float* __restrict__ Bv)
{
    extern __shared__ float sm[];
    int g = blockIdx.y;
    if (g == 0)      gcn3_body<5>(Y,Z,Wi,Bv,0,sm);
    else if (g <= 2) gcn3_body<6>(Y,Z,Wi,Bv,g,sm);
    else             gcn3_body<4>(Y,Z,Wi,Bv,g,sm);
}

// ---- tconv body (N real slots), dispatched per group ----
template<int COUT,int CRES,int MODE,int GCONV,int EMB,int N>
__device__ __forceinline__ void tconv_body(const float* __restrict__ Zin,
             const float* __restrict__ Yres, float* __restrict__ Yout,
             const float4* __restrict__ TWi, const float4* __restrict__ RWi,
             const float* __restrict__ CST, const float* __restrict__ BB0,
             const float* __restrict__ BB2,
             const float* __restrict__ GS, const float* __restrict__ BB,
             const float* __restrict__ EW, const float* __restrict__ EB,
             int g, float* sm)
{
    constexpr int CT  = COUT/8;
    constexpr int TH  = CT*16;
    constexpr int C4  = 16;
    constexpr int PRZ = 17;
    constexpr int TBL = 16;
    constexpr int WKT = 32*4*CT;
    constexpr int SBUF4 = (TBL+2)*N*PRZ;
    float4* sB4 = (float4*)sm;
    float4* sW4 = sB4 + SBUF4;
    const ulonglong2* sWl = (const ulonglong2*)sW4;
    float* sX  = (float*)(sW4 + WKT);
    float* sEW = sX + (TBL+2)*N*3;
    float* sEB = sEW + 192;
    __shared__ float sAdj[6][6];

    const int gs0 = c_gstart[g];
    const int bt0 = blockIdx.x * TBL;
    const int t0  = bt0 & (NT-1);
    const int tid = threadIdx.x, ty = tid/CT, tx = tid%CT;

    if (GCONV){
        if (tid < 36) sAdj[tid/6][tid%6] = g_adj[g][tid/6][tid%6];
    }
    if (EMB){
        for (int p=tid; p<192; p+=TH) sEW[p] = EW[p];
        for (int p=tid; p<64;  p+=TH) sEB[p] = EB[p];
        for (int p=tid; p<(TBL+2)*N; p+=TH){
            int u = p % N, hb = p / N;
            int t = t0 + hb - 1;
            float x0=0.f,x1=0.f,x2=0.f;
            if (t >= 0 && t < NT){
                int j = c_s2j[gs0+u];
                const float* xp = Zin + ((size_t)(bt0+hb-1)*25 + j)*3;
                x0=xp[0]; x1=xp[1]; x2=xp[2];
            }
            sX[p*3+0]=x0; sX[p*3+1]=x1; sX[p*3+2]=x2;
        }
    }
    if (GCONV || EMB) __syncthreads();

    if (EMB){
        for (int p=tid; p<(TBL+2)*C4; p+=TH){
            int c4 = p % C4, hb = p / C4;
            int t = t0 + hb - 1;
            bool valid = (t >= 0 && t < NT);
            float h[N][4];
            if (valid){
                #pragma unroll
                for (int vv=0; vv<N; ++vv){
                    const float* xr = sX + (hb*N+vv)*3;
                    float x0=xr[0], x1=xr[1], x2=xr[2];
                    #pragma unroll
                    for (int cc=0;cc<4;++cc){
                        int c = c4*4+cc;
                        h[vv][cc] = fmaf(x2, sEW[c*3+2],
                                    fmaf(x1, sEW[c*3+1],
                                    fmaf(x0, sEW[c*3+0], sEB[c])));
                    }
                }
            }
            #pragma unroll
            for (int uu=0; uu<N; ++uu){
                float4 v = make_float4(0.f,0.f,0.f,0.f);
                if (valid){
                    #pragma unroll
                    for (int vv=0; vv<N; ++vv){
                        float av = sAdj[uu][vv];
                        v.x = fmaf(av,h[vv][0],v.x);
                        v.y = fmaf(av,h[vv][1],v.y);
                        v.z = fmaf(av,h[vv][2],v.z);
                        v.w = fmaf(av,h[vv][3],v.w);
                    }
                }
                sB4[(hb*N+uu)*PRZ + c4] = v;
            }
        }
    } else if (GCONV){
        for (int p=tid; p<(TBL+2)*C4; p+=TH){
            int c4 = p % C4, hb = p / C4;
            int t = t0 + hb - 1;
            bool valid = (t >= 0 && t < NT);
            float4 yv[N];
            if (valid){
                const float4* yp = (const float4*)(Zin + ((size_t)(bt0+hb-1)*25 + gs0)*64) + c4;
                #pragma unroll
                for (int vv=0; vv<N; ++vv) yv[vv] = yp[(size_t)vv*C4];
            }
            #pragma unroll
            for (int uu=0; uu<N; ++uu){
                float4 v = make_float4(0.f,0.f,0.f,0.f);
                if (valid){
                    #pragma unroll
                    for (int vv=0; vv<N; ++vv){
                        float av = sAdj[uu][vv];
                        v.x += av*yv[vv].x; v.y += av*yv[vv].y;
                        v.z += av*yv[vv].z; v.w += av*yv[vv].w;
                    }
                }
                sB4[(hb*N+uu)*PRZ + c4] = v;
            }
        }
    } else {
        for (int p=tid; p<(TBL+2)*N*C4; p+=TH){
            int c4 = p % C4, r = p / C4, uu = r % N, hb = r / N;
            int t = t0 + hb - 1;
            float4 v = make_float4(0.f,0.f,0.f,0.f);
            if (t >= 0 && t < NT)
                v = ((const float4*)(Zin + ((size_t)(bt0+hb-1)*25 + gs0+uu)*64))[c4];
            sB4[r*PRZ + c4] = v;
        }
    }

    unsigned long long acc[N][4];
    unsigned long long z2 = pk2(0.f, 0.f);
    #pragma unroll
    for (int i=0;i<N;++i)
        #pragma unroll
        for (int jp=0;jp<4;++jp) acc[i][jp]=z2;

    const float4* TWg = TWi + (size_t)g*3*WKT;
    for (int kt=0;kt<3;++kt){
        __syncthreads();
        for (int p=tid; p<WKT; p+=TH) sW4[p] = TWg[kt*WKT + p];
        __syncthreads();
        #pragma unroll 8
        for (int kk4=0;kk4<C4;++kk4)
            gemm_kk4<CT,N>(acc, sB4 + (ty + N*kt)*PRZ + kk4, 16*PRZ,
                           sWl + 2*kk4*4*CT + tx);
    }

    if (MODE==1){
        constexpr int RPASS = CRES/64;
        constexpr int RWP   = 32*4*CT;
        const float4* RWg = RWi + (size_t)g*2048;
        for (int ph=0; ph<RPASS; ++ph){
            __syncthreads();
            for (int p=tid; p<TBL*N*16; p+=TH){
                int c4l = p % 16, r = p / 16, uu = r % N, t = r / N;
                float4 v = ((const float4*)(Yres + ((size_t)(bt0+t)*25 + gs0+uu)*CRES))[ph*16 + c4l];
                sB4[r*PRZ + c4l] = v;
            }
            for (int p=tid; p<RWP; p+=TH) sW4[p] = RWg[ph*RWP + p];
            __syncthreads();
            #pragma unroll 8
            for (int kk4l=0;kk4l<16;++kk4l)
                gemm_kk4<CT,N>(acc, sB4 + ty*PRZ + kk4l, 16*PRZ, sWl + 2*kk4l*4*CT + tx);
        }
    }

    float cst[8], gsv[8], bbv[8];
    #pragma unroll
    for (int jp=0;jp<4;++jp){
        int oa = tx + CT*2*jp;
        cst[2*jp]   = CST[g*COUT+oa];       cst[2*jp+1] = CST[g*COUT+oa+CT];
        gsv[2*jp]   = GS [g*COUT+oa]*BNS;   gsv[2*jp+1] = GS [g*COUT+oa+CT]*BNS;
        bbv[2*jp]   = BB [g*COUT+oa];       bbv[2*jp+1] = BB [g*COUT+oa+CT];
    }
    #pragma unroll
    for (int i=0;i<N;++i){
        int r = ty+16*i, t = r/N, u = r%N;
        size_t base = ((size_t)(bt0+t)*25 + gs0+u)*COUT;
        int tg = t0 + t;
        bool e0 = (tg==0), e2 = (tg==NT-1);
        const float* xr = EMB ? (sX + ((t+1)*N+u)*3) : (const float*)0;
        float x0=0.f,x1=0.f,x2=0.f;
        if (EMB){ x0=xr[0]; x1=xr[1]; x2=xr[2]; }
        #pragma unroll
        for (int jp=0;jp<4;++jp){
            float lo,hi; unpk(acc[i][jp], lo, hi);
            int oa = tx + CT*2*jp;
            int ob = oa + CT;
            float pa = lo + cst[2*jp];
            float pb = hi + cst[2*jp+1];
            if (e0){ pa -= BB0[g*COUT+oa]; pb -= BB0[g*COUT+ob]; }
            if (e2){ pa -= BB2[g*COUT+oa]; pb -= BB2[g*COUT+ob]; }
            if (MODE==0){
                if (EMB){
                    pa += fmaf(x2,sEW[oa*3+2], fmaf(x1,sEW[oa*3+1], fmaf(x0,sEW[oa*3+0], sEB[oa])));
                    pb += fmaf(x2,sEW[ob*3+2], fmaf(x1,sEW[ob*3+1], fmaf(x0,sEW[ob*3+0], sEB[ob])));
                } else {
                    pa += Yres[base+oa]; pb += Yres[base+ob];
                }
            }
            Yout[base+oa] = fmaxf(pa*gsv[2*jp]   + bbv[2*jp],   0.f);
            Yout[base+ob] = fmaxf(pb*gsv[2*jp+1] + bbv[2*jp+1], 0.f);
        }
    }
}

template<int COUT,int CRES,int MODE,int GCONV,int EMB>
__global__ __launch_bounds__((COUT/8)*16)
void k_tconv(const float* __restrict__ Zin, const float* __restrict__ Yres,
             float* __restrict__ Yout,
             const float4* __restrict__ TWi, const float4* __restrict__ RWi,
             const float* __restrict__ CST, const float* __restrict__ BB0,
             const float* __restrict__ BB2,
             const float* __restrict__ GS, const float* __restrict__ BB,
             const float* __restrict__ EW, const float* __restrict__ EB)
{
    extern __shared__ float sm[];
    int g = blockIdx.y;
    if (g == 0)
        tconv_body<COUT,CRES,MODE,GCONV,EMB,5>(Zin,Yres,Yout,TWi,RWi,CST,BB0,BB2,GS,BB,EW,EB,0,sm);
    else if (g <= 2)
        tconv_body<COUT,CRES,MODE,GCONV,EMB,6>(Zin,Yres,Yout,TWi,RWi,CST,BB0,BB2,GS,BB,EW,EB,g,sm);
    else
        tconv_body<COUT,CRES,MODE,GCONV,EMB,4>(Zin,Yres,Yout,TWi,RWi,CST,BB0,BB2,GS,BB,EW,EB,g,sm);
}

__global__ __launch_bounds__(256) void k_featvq(const float* __restrict__ cb,
                                                float* __restrict__ out)
{
    int g = blockIdx.x, b = blockIdx.y;
    int tid = threadIdx.x;
    int o = tid & 63, part = tid >> 6;
    int n = c_gn[g], gs0 = c_gstart[g];
    float s = 0.f;
    int total = NT*n;
    for (int q=part; q<total; q+=4){
        int t = q / n, u = q % n;
        s += g_Y3[((size_t)(b*NT+t)*25 + gs0+u)*64 + o];
    }
    __shared__ float red[256];
    __shared__ float f[64];
    red[tid]=s; __syncthreads();
    if (part==0)
        f[o] = (red[o]+red[64+o]+red[128+o]+red[192+o]) / (float)(NT*n);
    __syncthreads();

    __shared__ float ds[128];
    __shared__ int   sidx;
    if (tid < 128){
        const float* ck = cb + (g*128 + tid)*64;
        float dot=0.f, scb=0.f;
        for (int oo=0;oo<64;++oo){ dot += f[oo]*ck[oo]; scb += ck[oo]*ck[oo]; }
        ds[tid] = scb - 2.f*dot;
    }
    __syncthreads();
    if (tid==0){
        float best = ds[0]; int bi = 0;
        for (int kk=1;kk<128;++kk) if (ds[kk] < best){ best = ds[kk]; bi = kk; }
        sidx = bi;
    }
    __syncthreads();
    int idx = sidx;
    __shared__ float dsq[64];
    if (tid < 64){
        float q = cb[(g*128 + idx)*64 + tid];
        out[(g*64+b)*64 + tid] = q;
        float dd = q - f[tid];
        dsq[tid] = dd*dd;
    }
    __syncthreads();
    if (tid==0){
        float ss=0.f;
        for (int oo=0;oo<64;++oo) ss += dsq[oo];
        g_loss[g*64+b] = 1.25f * ss / 4096.f;
        out[5*64*64 + 1 + g*64 + b] = (float)idx;
    }
}

__global__ void k_lred(float* out){
    __shared__ float s[320];
    int t = threadIdx.x;
    if (t < 320) s[t] = g_loss[t];
    __syncthreads();
    if (t==0){
        float a=0.f;
        for (int i=0;i<320;i++) a += s[i];
        out[5*64*64] = a;
    }
}

extern "C" void kernel_launch(void* const* d_in, const int* in_sizes, int n_in,
                              void* d_out, int out_size)
{
    const float* x        = (const float*)d_in[0];
    const float* embed_w  = (const float*)d_in[1];
    const float* embed_b  = (const float*)d_in[2];
    const float* sgcn_w1  = (const float*)d_in[3];
    const float* sgcn_b1  = (const float*)d_in[4];
    const float* tconv_w1 = (const float*)d_in[5];
    const float* tconv_b1 = (const float*)d_in[6];
    const float* bn_g1    = (const float*)d_in[7];
    const float* bn_b1    = (const float*)d_in[8];
    const float* res_w2   = (const float*)d_in[9];
    const float* res_b2   = (const float*)d_in[10];
    const float* resbn_g2 = (const float*)d_in[11];
    const float* resbn_b2 = (const float*)d_in[12];
    const float* sgcn_w2  = (const float*)d_in[13];
    const float* sgcn_b2  = (const float*)d_in[14];
    const float* tconv_w2 = (const float*)d_in[15];
    const float* tconv_b2 = (const float*)d_in[16];
    const float* bn_g2    = (const float*)d_in[17];
    const float* bn_b2    = (const float*)d_in[18];
    const float* res_w3   = (const float*)d_in[19];
    const float* res_b3   = (const float*)d_in[20];
    const float* resbn_g3 = (const float*)d_in[21];
    const float* resbn_b3 = (const float*)d_in[22];
    const float* sgcn_w3  = (const float*)d_in[23];
    const float* sgcn_b3  = (const float*)d_in[24];
    const float* tconv_w3 = (const float*)d_in[25];
    const float* tconv_b3 = (const float*)d_in[26];
    const float* bn_g3    = (const float*)d_in[27];
    const float* bn_b3    = (const float*)d_in[28];
    const float* codebooks= (const float*)d_in[29];
    float* out = (float*)d_out;

    void *vp;
    #define SYM(name, s, T) cudaGetSymbolAddress(&vp, s); T* name = (T*)vp;
    SYM(pZ, g_Z, float)  SYM(pY1, g_Y1, float)
    SYM(pY2, g_Y2, float)  SYM(pY3, g_Y3, float)
    SYM(pSB3,g_sb3,float)
    SYM(pC1, g_cst1,float) SYM(pB01,g_bb0_1,float) SYM(pB21,g_bb2_1,float)
    SYM(pC2, g_cst2,float) SYM(pB02,g_bb0_2,float) SYM(pB22,g_bb2_2,float)
    SYM(pC3, g_cst3,float) SYM(pZERO,g_zero,float)
    SYM(pSW3,g_sw3i,float4)
    SYM(pRW2,g_rw2i,float4) SYM(pRW3,g_rw3i,float4)
    SYM(pTW1,g_tw1i,float4) SYM(pTW2,g_tw2i,float4) SYM(pTW3,g_tw3i,float4)
    #undef SYM

    dim3 grid16(BT/16, 5);
    dim3 grid32(BT/32, 5);

    // smem sized for N=6
    size_t sm_t1 = (size_t)(18*6*17 + 1024)*16 + (18*6*3 + 192 + 64)*4;
    size_t sm_t2 = (size_t)(18*6*17 + 2048)*16;
    size_t sm_t3 = (size_t)(18*6*17 + 1024)*16;
    size_t sm_g3 = (size_t)(32*6*17 + 1024)*16;

    cudaFuncSetAttribute((k_tconv<64,64,0,1,1>),   cudaFuncAttributeMaxDynamicSharedMemorySize, (int)sm_t1);
    cudaFuncSetAttribute((k_tconv<128,64,1,1,0>),  cudaFuncAttributeMaxDynamicSharedMemorySize, (int)sm_t2);
    cudaFuncSetAttribute(k_gcn3,                   cudaFuncAttributeMaxDynamicSharedMemorySize, (int)sm_g3);
    cudaFuncSetAttribute((k_tconv<64,128,1,0,0>),  cudaFuncAttributeMaxDynamicSharedMemorySize, (int)sm_t3);

    k_prep<<<64,256>>>(sgcn_w1, sgcn_b1, tconv_w1, tconv_b1,
                       res_w2, res_b2, resbn_g2, resbn_b2, sgcn_w2, sgcn_b2, tconv_w2, tconv_b2,
                       res_w3, res_b3, resbn_g3, resbn_b3, sgcn_w3, sgcn_b3, tconv_w3, tconv_b3);

    k_tconv<64,64,0,1,1><<<grid16,128,sm_t1>>>(x, x, pY1, pTW1, pRW2,
                                               pC1, pB01, pB21, bn_g1, bn_b1, embed_w, embed_b);
    k_tconv<128,64,1,1,0><<<grid16,256,sm_t2>>>(pY1, pY1, pY2, pTW2, pRW2,
                                                pC2, pB02, pB22, bn_g2, bn_b2, nullptr, nullptr);
    k_gcn3<<<grid32,256,sm_g3>>>(pY2, pZ, pSW3, pSB3);
    k_tconv<64,128,1,0,0><<<grid16,128,sm_t3>>>(pZ, pY2, pY3, pTW3, pRW3,
                                                pC3, pZERO, pZERO, bn_g3, bn_b3, nullptr, nullptr);

    k_featvq<<<dim3(5,64),256>>>(codebooks, out);
    k_lred<<<1,512>>>(out);
}

// round 16
// speedup vs baseline: 1.3733x; 1.0523x over previous
#include <cuda_runtime.h>

#define NB 64
#define NT 256
#define BT (NB*NT)
#define BNS 0.9999950000374997f

__constant__ int c_s2j[25] = {0,1,2,3,20, 4,5,6,7,21,22, 8,9,10,11,23,24, 12,13,14,15, 16,17,18,19};
__constant__ int c_gstart[5] = {0,5,11,17,21};
__constant__ int c_gn[5]     = {5,6,6,4,4};

__device__ float g_adj[5][6][6];
__device__ float g_Z [BT*25*64];
__device__ float g_Y1[BT*25*64];
__device__ float g_Y2[BT*25*128];
__device__ float g_Y3[BT*25*64];
__device__ float g_psum[5*64*16*64];
__device__ float g_loss[5*64];
__device__ float g_sb3[5*64];
__device__ float g_cst1[5*64],  g_bb0_1[5*64],  g_bb2_1[5*64];
__device__ float g_cst2[5*128], g_bb0_2[5*128], g_bb2_2[5*128];
__device__ float g_cst3[5*64];
__device__ float g_zero[640];
__device__ float4 g_sw3i[10240];
__device__ float4 g_rw2i[10240];
__device__ float4 g_rw3i[10240];
__device__ float4 g_tw1i[15360];
__device__ float4 g_tw2i[30720];
__device__ float4 g_tw3i[15360];

__device__ __forceinline__ unsigned long long bc2(float x){
    unsigned long long r; unsigned u = __float_as_uint(x);
    asm("mov.b64 %0, {%1, %1};" : "=l"(r) : "r"(u));
    return r;
}
__device__ __forceinline__ unsigned long long pk2(float a, float b){
    unsigned long long r;
    asm("mov.b64 %0, {%1, %2};" : "=l"(r) : "r"(__float_as_uint(a)), "r"(__float_as_uint(b)));
    return r;
}
__device__ __forceinline__ void ffma2(unsigned long long& c, unsigned long long a, unsigned long long b){
    asm("fma.rn.f32x2 %0, %1, %2, %0;" : "+l"(c) : "l"(a), "l"(b));
}
__device__ __forceinline__ void unpk(unsigned long long v, float& lo, float& hi){
    unsigned a,b; asm("mov.b64 {%0, %1}, %2;" : "=r"(a), "=r"(b) : "l"(v));
    lo = __uint_as_float(a); hi = __uint_as_float(b);
}

__global__ __launch_bounds__(256) void k_prep(
    const float* __restrict__ sw1, const float* __restrict__ sb1,
    const float* __restrict__ tw1, const float* __restrict__ tb1,
    const float* __restrict__ rw2, const float* __restrict__ rb2,
    const float* __restrict__ rg2, const float* __restrict__ rbb2,
    const float* __restrict__ sw2, const float* __restrict__ sb2,
    const float* __restrict__ tw2, const float* __restrict__ tb2,
    const float* __restrict__ rw3, const float* __restrict__ rb3,
    const float* __restrict__ rg3, const float* __restrict__ rbb3,
    const float* __restrict__ sw3, const float* __restrict__ sb3,
    const float* __restrict__ tw3, const float* __restrict__ tb3)
{
    int gt  = blockIdx.x*blockDim.x + threadIdx.x;
    int NTH = gridDim.x*blockDim.x;

    for (int e=gt;e<15360;e+=NTH){
        int g=e/3072, r=e%3072, kt=r/1024, r2=r%1024, kk2=r2/32, q=r2%32, jp=q/8, tx=q%8;
        int oa=tx+16*jp, ob=oa+8, k0=2*kk2;
        float v0=0.f,v1=0.f,v2=0.f,v3=0.f;
        for (int c=0;c<64;c++){
            float s0 = sw1[(g*192+c)*64+k0]   + sw1[(g*192+64+c)*64+k0]   + sw1[(g*192+128+c)*64+k0];
            float s1 = sw1[(g*192+c)*64+k0+1] + sw1[(g*192+64+c)*64+k0+1] + sw1[(g*192+128+c)*64+k0+1];
            float wa = tw1[((g*64+oa)*64+c)*3+kt];
            float wb = tw1[((g*64+ob)*64+c)*3+kt];
            v0=fmaf(wa,s0,v0); v1=fmaf(wb,s0,v1); v2=fmaf(wa,s1,v2); v3=fmaf(wb,s1,v3);
        }
        g_tw1i[e]=make_float4(v0,v1,v2,v3);
    }
    for (int e=gt;e<15360;e+=NTH){
        int g=e/3072, r=e%3072, kt=r/1024, r2=r%1024, kk2=r2/32, q=r2%32, jp=q/8, tx=q%8;
        int oa=tx+16*jp, ob=oa+8, k0=2*kk2;
        g_tw3i[e]=make_float4(tw3[((g*64+oa)*64+k0)*3+kt],   tw3[((g*64+ob)*64+k0)*3+kt],
                              tw3[((g*64+oa)*64+k0+1)*3+kt], tw3[((g*64+ob)*64+k0+1)*3+kt]);
    }
    for (int e=gt;e<30720;e+=NTH){
        int g=e/6144, r=e%6144, kt=r/2048, r2=r%2048, kk2=r2/64, q=r2%64, jp=q/16, tx=q%16;
        int oa=tx+32*jp, ob=oa+16, k0=2*kk2;
        float v0=0.f,v1=0.f,v2=0.f,v3=0.f;
        for (int c=0;c<128;c++){
            float s0 = sw2[(g*384+c)*64+k0]   + sw2[(g*384+128+c)*64+k0]   + sw2[(g*384+256+c)*64+k0];
            float s1 = sw2[(g*384+c)*64+k0+1] + sw2[(g*384+128+c)*64+k0+1] + sw2[(g*384+256+c)*64+k0+1];
            float wa = tw2[((g*128+oa)*128+c)*3+kt];
            float wb = tw2[((g*128+ob)*128+c)*3+kt];
            v0=fmaf(wa,s0,v0); v1=fmaf(wb,s0,v1); v2=fmaf(wa,s1,v2); v3=fmaf(wb,s1,v3);
        }
        g_tw2i[e]=make_float4(v0,v1,v2,v3);
    }
    for (int e=gt;e<10240;e+=NTH){
        int g=e/2048, r=e%2048, kk2=r/32, q=r%32, jp=q/8, tx=q%8;
        int oa=tx+16*jp, ob=oa+8, k0=2*kk2;
        const float* w = sw3 + g*192*128;
        #define S3(o,c) (w[(o)*128+(c)] + w[(64+(o))*128+(c)] + w[(128+(o))*128+(c)])
        g_sw3i[e] = make_float4(S3(oa,k0), S3(ob,k0), S3(oa,k0+1), S3(ob,k0+1));
        #undef S3
    }
    for (int e=gt;e<10240;e+=NTH){
        int g=e/2048, r=e%2048, kk2=r/64, q=r%64, jp=q/16, tx=q%16;
        int oa=tx+32*jp, ob=oa+16, k0=2*kk2;
        const float* w = rw2 + g*8192;
        float sa_=rg2[g*128+oa]*BNS, sb_=rg2[g*128+ob]*BNS;
        g_rw2i[e] = make_float4(w[oa*64+k0]*sa_, w[ob*64+k0]*sb_, w[oa*64+k0+1]*sa_, w[ob*64+k0+1]*sb_);
    }
    for (int e=gt;e<10240;e+=NTH){
        int g=e/2048, r=e%2048, kk2=r/32, q=r%32, jp=q/8, tx=q%8;
        int oa=tx+16*jp, ob=oa+8, k0=2*kk2;
        const float* w = rw3 + g*8192;
        float sa_=rg3[g*64+oa]*BNS, sb_=rg3[g*64+ob]*BNS;
        g_rw3i[e] = make_float4(w[oa*128+k0]*sa_, w[ob*128+k0]*sb_, w[oa*128+k0+1]*sa_, w[ob*128+k0+1]*sb_);
    }
    for (int i=gt;i<5*64;i+=NTH){
        int g=i/64, o=i%64;
        float b0=0.f,b1=0.f,b2=0.f;
        for (int c=0;c<64;c++){
            float sb = sb1[g*192+c]+sb1[g*192+64+c]+sb1[g*192+128+c];
            b0=fmaf(tw1[((g*64+o)*64+c)*3+0],sb,b0);
            b1=fmaf(tw1[((g*64+o)*64+c)*3+1],sb,b1);
            b2=fmaf(tw1[((g*64+o)*64+c)*3+2],sb,b2);
        }
        g_cst1[i]=tb1[i]+b0+b1+b2;
        g_bb0_1[i]=b0; g_bb2_1[i]=b2;
        const float* s3=sb3+g*192;
        g_sb3[i]=s3[o]+s3[64+o]+s3[128+o];
        g_cst3[i]=tb3[i]+rb3[i]*rg3[i]*BNS+rbb3[i];
    }
    for (int i=gt;i<5*128;i+=NTH){
        int g=i/128, o=i%128;
        float b0=0.f,b1=0.f,b2=0.f;
        for (int c=0;c<128;c++){
            float sb = sb2[g*384+c]+sb2[g*384+128+c]+sb2[g*384+256+c];
            b0=fmaf(tw2[((g*128+o)*128+c)*3+0],sb,b0);
            b1=fmaf(tw2[((g*128+o)*128+c)*3+1],sb,b1);
            b2=fmaf(tw2[((g*128+o)*128+c)*3+2],sb,b2);
        }
        g_cst2[i]=tb2[i]+rb2[i]*rg2[i]*BNS+rbb2[i]+b0+b1+b2;
        g_bb0_2[i]=b0; g_bb2_2[i]=b2;
    }
    for (int i=gt;i<640;i+=NTH) g_zero[i]=0.f;
    if (gt==0){
        double fa[25][25];
        for (int i=0;i<25;i++) for (int j=0;j<25;j++) fa[i][j]=0.0;
        const int E[24][2]={{3,2},{2,20},{20,1},{1,0},{20,4},{4,5},{5,6},{6,22},
                            {6,7},{7,21},{20,8},{8,9},{9,10},{10,24},{10,11},{11,23},
                            {0,12},{12,13},{13,14},{14,15},{0,16},{16,17},{17,18},{18,19}};
        for (int k=0;k<24;k++){
            int i=E[k][0]-1, j=E[k][1]-1;
            fa[i][j]=1.0; fa[j][i]=1.0;
        }
        for (int i=0;i<25;i++) fa[i][i]+=1.0;
        for (int i=0;i<25;i++){
            double d=0; for (int j=0;j<25;j++) d+=fa[i][j];
            if (d==0.0) d=1.0;
            for (int j=0;j<25;j++) fa[i][j]/=d;
        }
        for (int g=0;g<5;g++){
            int n=c_gn[g];
            int js[6]; for (int u=0;u<n;u++) js[u]=c_s2j[c_gstart[g]+u];
            double sa[6][6];
            for (int u=0;u<n;u++) for (int v=0;v<n;v++) sa[u][v]=fa[js[u]][js[v]];
            for (int u=0;u<n;u++) sa[u][u]+=1.0;
            double dg[6];
            for (int u=0;u<n;u++){ double d=0; for (int v=0;v<n;v++) d+=sa[u][v]; dg[u]=d; }
            for (int node=1;node<n;node++)
                if (dg[node]==1.0){ sa[0][node]=1.0; sa[node][0]=1.0; }
            for (int u=0;u<6;u++) for (int v=0;v<6;v++){
                float val=0.f;
                if (u<n && v<n){
                    double d=0; for (int w=0;w<n;w++) d+=sa[u][w];
                    if (d==0.0) d=1.0;
                    val=(float)(sa[u][v]/d);
                }
                g_adj[g][u][v]=val;
            }
        }
    }
}

template<int CT,int NR>
__device__ __forceinline__ void gemm_kk4(unsigned long long (&acc)[NR][4],
                                         const float4* aPtr, int aStride,
                                         const ulonglong2* wPtr)
{
    float4 a[NR];
    #pragma unroll
    for (int i=0;i<NR;++i) a[i] = aPtr[aStride*i];
    #pragma unroll
    for (int h=0;h<2;++h){
        ulonglong2 w0 = wPtr[h*4*CT + 0*CT];
        ulonglong2 w1 = wPtr[h*4*CT + 1*CT];
        ulonglong2 w2 = wPtr[h*4*CT + 2*CT];
        ulonglong2 w3 = wPtr[h*4*CT + 3*CT];
        #pragma unroll
        for (int i=0;i<NR;++i){
            unsigned long long alo = bc2(h ? a[i].z : a[i].x);
            unsigned long long ahi = bc2(h ? a[i].w : a[i].y);
            ffma2(acc[i][0], alo, w0.x);
            ffma2(acc[i][1], alo, w1.x);
            ffma2(acc[i][2], alo, w2.x);
            ffma2(acc[i][3], alo, w3.x);
            ffma2(acc[i][0], ahi, w0.y);
            ffma2(acc[i][1], ahi, w1.y);
            ffma2(acc[i][2], ahi, w2.y);
            ffma2(acc[i][3], ahi, w3.y);
        }
    }
}

// ---- Layer-3 GCN body: TBL=16, 128 threads, 4 CTAs/SM ----
template<int N>
__device__ __forceinline__ void gcn3_body(const float* __restrict__ Y,
                                          float* __restrict__ Z,
                                          const float4* __restrict__ Wi,
                                          const float* __restrict__ Bv,
                                          int g, float* sm)
{
    constexpr int CT = 8;
    float4* sA4 = (float4*)sm;                 // [16*N][17]
    float4* sW4 = sA4 + 16*N*17;               // [1024]
    const ulonglong2* sWl = (const ulonglong2*)sW4;
    __shared__ float sAdj[6][6];

    const int gs0 = c_gstart[g];
    const int bt0 = blockIdx.x * 16;
    const int tid = threadIdx.x;
    if (tid < 36) sAdj[tid/6][tid%6] = g_adj[g][tid/6][tid%6];

    const int ty = tid / CT, tx = tid % CT;
    unsigned long long acc[N][4];
    #pragma unroll
    for (int jp=0;jp<4;++jp){
        int oa = tx + 16*jp;
        unsigned long long b2 = pk2(Bv[g*64+oa], Bv[g*64+oa+8]);
        #pragma unroll
        for (int i=0;i<N;++i) acc[i][jp]=b2;
    }
    const float4* Wg = Wi + (size_t)g*2048;

    for (int ph=0; ph<2; ++ph){
        __syncthreads();
        for (int p=tid; p<16*16; p+=128){
            int c4l = p % 16, t = p / 16;
            int c4 = ph*16 + c4l;
            const float4* yp = (const float4*)(Y + ((size_t)(bt0+t)*25 + gs0)*128) + c4;
            float4 yv[N];
            #pragma unroll
            for (int vv=0; vv<N; ++vv) yv[vv] = yp[(size_t)vv*32];
            #pragma unroll
            for (int uu=0; uu<N; ++uu){
                float4 v = make_float4(0.f,0.f,0.f,0.f);
                #pragma unroll
                for (int vv=0; vv<N; ++vv){
                    float av = sAdj[uu][vv];
                    v.x += av*yv[vv].x; v.y += av*yv[vv].y;
                    v.z += av*yv[vv].z; v.w += av*yv[vv].w;
                }
                sA4[(t*N+uu)*17 + c4l] = v;
            }
        }
        for (int p=tid; p<1024; p+=128) sW4[p] = Wg[ph*1024 + p];
        __syncthreads();
        #pragma unroll 8
        for (int kk4l=0;kk4l<16;++kk4l)
            gemm_kk4<CT,N>(acc, sA4 + ty*17 + kk4l, 16*17, sWl + 2*kk4l*4*CT + tx);
    }

    #pragma unroll
    for (int i=0;i<N;++i){
        int r = ty+16*i, t = r/N, u = r%N;
        float* zp = Z + ((size_t)(bt0+t)*25 + gs0+u)*64;
        #pragma unroll
        for (int jp=0;jp<4;++jp){
            float lo,hi; unpk(acc[i][jp], lo, hi);
            int oa = tx + 16*jp;
            zp[oa] = lo; zp[oa+8] = hi;
        }
    }
}

__global__ __launch_bounds__(128,4) void k_gcn3(const float* __restrict__ Y,
                                                float* __restrict__ Z,
                                                const float4* __restrict__ Wi,
                                                const float* __restrict__ Bv)
{
    extern __shared__ float sm[];
    int g = blockIdx.y;
    if (g == 0)      gcn3_body<5>(Y,Z,Wi,Bv,0,sm);
    else if (g <= 2) gcn3_body<6>(Y,Z,Wi,Bv,g,sm);
    else             gcn3_body<4>(Y,Z,Wi,Bv,g,sm);
}

// ---- tconv body (N real slots); PSUM=1 emits deterministic per-tile partial sums ----
template<int COUT,int CRES,int MODE,int GCONV,int EMB,int PSUM,int N>
__device__ __forceinline__ void tconv_body(const float* __restrict__ Zin,
             const float* __restrict__ Yres, float* __restrict__ Yout,
             const float4* __restrict__ TWi, const float4* __restrict__ RWi,
             const float* __restrict__ CST, const float* __restrict__ BB0,
             const float* __restrict__ BB2,
             const float* __restrict__ GS, const float* __restrict__ BB,
             const float* __restrict__ EW, const float* __restrict__ EB,
             int g, float* sm)
{
    constexpr int CT  = COUT/8;
    constexpr int TH  = CT*16;
    constexpr int C4  = 16;
    constexpr int PRZ = 17;
    constexpr int TBL = 16;
    constexpr int WKT = 32*4*CT;
    constexpr int SBUF4 = (TBL+2)*N*PRZ;
    float4* sB4 = (float4*)sm;
    float4* sW4 = sB4 + SBUF4;
    const ulonglong2* sWl = (const ulonglong2*)sW4;
    float* sX  = (float*)(sW4 + WKT);
    float* sEW = sX + (TBL+2)*N*3;
    float* sEB = sEW + 192;
    __shared__ float sAdj[6][6];

    const int gs0 = c_gstart[g];
    const int bt0 = blockIdx.x * TBL;
    const int t0  = bt0 & (NT-1);
    const int tid = threadIdx.x, ty = tid/CT, tx = tid%CT;

    if (GCONV){
        if (tid < 36) sAdj[tid/6][tid%6] = g_adj[g][tid/6][tid%6];
    }
    if (EMB){
        for (int p=tid; p<192; p+=TH) sEW[p] = EW[p];
        for (int p=tid; p<64;  p+=TH) sEB[p] = EB[p];
        for (int p=tid; p<(TBL+2)*N; p+=TH){
            int u = p % N, hb = p / N;
            int t = t0 + hb - 1;
            float x0=0.f,x1=0.f,x2=0.f;
            if (t >= 0 && t < NT){
                int j = c_s2j[gs0+u];
                const float* xp = Zin + ((size_t)(bt0+hb-1)*25 + j)*3;
                x0=xp[0]; x1=xp[1]; x2=xp[2];
            }
            sX[p*3+0]=x0; sX[p*3+1]=x1; sX[p*3+2]=x2;
        }
    }
    if (GCONV || EMB) __syncthreads();

    if (EMB){
        for (int p=tid; p<(TBL+2)*C4; p+=TH){
            int c4 = p % C4, hb = p / C4;
            int t = t0 + hb - 1;
            bool valid = (t >= 0 && t < NT);
            float h[N][4];
            if (valid){
                #pragma unroll
                for (int vv=0; vv<N; ++vv){
                    const float* xr = sX + (hb*N+vv)*3;
                    float x0=xr[0], x1=xr[1], x2=xr[2];
                    #pragma unroll
                    for (int cc=0;cc<4;++cc){
                        int c = c4*4+cc;
                        h[vv][cc] = fmaf(x2, sEW[c*3+2],
                                    fmaf(x1, sEW[c*3+1],
                                    fmaf(x0, sEW[c*3+0], sEB[c])));
                    }
                }
            }
            #pragma unroll
            for (int uu=0; uu<N; ++uu){
                float4 v = make_float4(0.f,0.f,0.f,0.f);
                if (valid){
                    #pragma unroll
                    for (int vv=0; vv<N; ++vv){
                        float av = sAdj[uu][vv];
                        v.x = fmaf(av,h[vv][0],v.x);
                        v.y = fmaf(av,h[vv][1],v.y);
                        v.z = fmaf(av,h[vv][2],v.z);
                        v.w = fmaf(av,h[vv][3],v.w);
                    }
                }
                sB4[(hb*N+uu)*PRZ + c4] = v;
            }
        }
    } else if (GCONV){
        for (int p=tid; p<(TBL+2)*C4; p+=TH){
            int c4 = p % C4, hb = p / C4;
            int t = t0 + hb - 1;
            bool valid = (t >= 0 && t < NT);
            float4 yv[N];
            if (valid){
                const float4* yp = (const float4*)(Zin + ((size_t)(bt0+hb-1)*25 + gs0)*64) + c4;
                #pragma unroll
                for (int vv=0; vv<N; ++vv) yv[vv] = yp[(size_t)vv*C4];
            }
            #pragma unroll
            for (int uu=0; uu<N; ++uu){
                float4 v = make_float4(0.f,0.f,0.f,0.f);
                if (valid){
                    #pragma unroll
                    for (int vv=0; vv<N; ++vv){
                        float av = sAdj[uu][vv];
                        v.x += av*yv[vv].x; v.y += av*yv[vv].y;
                        v.z += av*yv[vv].z; v.w += av*yv[vv].w;
                    }
                }
                sB4[(hb*N+uu)*PRZ + c4] = v;
            }
        }
    } else {
        for (int p=tid; p<(TBL+2)*N*C4; p+=TH){
            int c4 = p % C4, r = p / C4, uu = r % N, hb = r / N;
            int t = t0 + hb - 1;
            float4 v = make_float4(0.f,0.f,0.f,0.f);
            if (t >= 0 && t < NT)
                v = ((const float4*)(Zin + ((size_t)(bt0+hb-1)*25 + gs0+uu)*64))[c4];
            sB4[r*PRZ + c4] = v;
        }
    }

    unsigned long long acc[N][4];
    unsigned long long z2 = pk2(0.f, 0.f);
    #pragma unroll
    for (int i=0;i<N;++i)
        #pragma unroll
        for (int jp=0;jp<4;++jp) acc[i][jp]=z2;

    const float4* TWg = TWi + (size_t)g*3*WKT;
    for (int kt=0;kt<3;++kt){
        __syncthreads();
        for (int p=tid; p<WKT; p+=TH) sW4[p] = TWg[kt*WKT + p];
        __syncthreads();
        #pragma unroll 8
        for (int kk4=0;kk4<C4;++kk4)
            gemm_kk4<CT,N>(acc, sB4 + (ty + N*kt)*PRZ + kk4, 16*PRZ,
                           sWl + 2*kk4*4*CT + tx);
    }

    if (MODE==1){
        constexpr int RPASS = CRES/64;
        constexpr int RWP   = 32*4*CT;
        const float4* RWg = RWi + (size_t)g*2048;
        for (int ph=0; ph<RPASS; ++ph){
            __syncthreads();
            for (int p=tid; p<TBL*N*16; p+=TH){
                int c4l = p % 16, r = p / 16, uu = r % N, t = r / N;
                float4 v = ((const float4*)(Yres + ((size_t)(bt0+t)*25 + gs0+uu)*CRES))[ph*16 + c4l];
                sB4[r*PRZ + c4l] = v;
            }
            for (int p=tid; p<RWP; p+=TH) sW4[p] = RWg[ph*RWP + p];
            __syncthreads();
            #pragma unroll 8
            for (int kk4l=0;kk4l<16;++kk4l)
                gemm_kk4<CT,N>(acc, sB4 + ty*PRZ + kk4l, 16*PRZ, sWl + 2*kk4l*4*CT + tx);
        }
    }

    float cst[8], gsv[8], bbv[8];
    #pragma unroll
    for (int jp=0;jp<4;++jp){
        int oa = tx + CT*2*jp;
        cst[2*jp]   = CST[g*COUT+oa];       cst[2*jp+1] = CST[g*COUT+oa+CT];
        gsv[2*jp]   = GS [g*COUT+oa]*BNS;   gsv[2*jp+1] = GS [g*COUT+oa+CT]*BNS;
        bbv[2*jp]   = BB [g*COUT+oa];       bbv[2*jp+1] = BB [g*COUT+oa+CT];
    }
    float part[8];
    #pragma unroll
    for (int q=0;q<8;++q) part[q]=0.f;
    #pragma unroll
    for (int i=0;i<N;++i){
        int r = ty+16*i, t = r/N, u = r%N;
        size_t base = ((size_t)(bt0+t)*25 + gs0+u)*COUT;
        int tg = t0 + t;
        bool e0 = (tg==0), e2 = (tg==NT-1);
        const float* xr = EMB ? (sX + ((t+1)*N+u)*3) : (const float*)0;
        float x0=0.f,x1=0.f,x2=0.f;
        if (EMB){ x0=xr[0]; x1=xr[1]; x2=xr[2]; }
        #pragma unroll
        for (int jp=0;jp<4;++jp){
            float lo,hi; unpk(acc[i][jp], lo, hi);
            int oa = tx + CT*2*jp;
            int ob = oa + CT;
            float pa = lo + cst[2*jp];
            float pb = hi + cst[2*jp+1];
            if (e0){ pa -= BB0[g*COUT+oa]; pb -= BB0[g*COUT+ob]; }
            if (e2){ pa -= BB2[g*COUT+oa]; pb -= BB2[g*COUT+ob]; }
            if (MODE==0){
                if (EMB){
                    pa += fmaf(x2,sEW[oa*3+2], fmaf(x1,sEW[oa*3+1], fmaf(x0,sEW[oa*3+0], sEB[oa])));
                    pb += fmaf(x2,sEW[ob*3+2], fmaf(x1,sEW[ob*3+1], fmaf(x0,sEW[ob*3+0], sEB[ob])));
                } else {
                    pa += Yres[base+oa]; pb += Yres[base+ob];
                }
            }
            float ra = fmaxf(pa*gsv[2*jp]   + bbv[2*jp],   0.f);
            float rb = fmaxf(pb*gsv[2*jp+1] + bbv[2*jp+1], 0.f);
            Yout[base+oa] = ra;
            Yout[base+ob] = rb;
            if (PSUM){ part[2*jp] += ra; part[2*jp+1] += rb; }
        }
    }
    if (PSUM){
        float* sP = (float*)sB4;   // 16*64 floats, sB4 no longer needed
        __syncthreads();
        #pragma unroll
        for (int jp=0;jp<4;++jp){
            int oa = tx + CT*2*jp;
            sP[ty*64 + oa]      = part[2*jp];
            sP[ty*64 + oa + CT] = part[2*jp+1];
        }
        __syncthreads();
        if (tid < 64){
            float s = 0.f;
            #pragma unroll
            for (int yy=0; yy<16; ++yy) s += sP[yy*64 + tid];
            int b    = bt0 / NT;
            int tile = t0 / 16;
            g_psum[(((size_t)g*64 + b)*16 + tile)*64 + tid] = s;
        }
    }
}

template<int COUT,int CRES,int MODE,int GCONV,int EMB,int PSUM>
__global__ __launch_bounds__((COUT/8)*16)
void k_tconv(const float* __restrict__ Zin, const float* __restrict__ Yres,
             float* __restrict__ Yout,
             const float4* __restrict__ TWi, const float4* __restrict__ RWi,
             const float* __restrict__ CST, const float* __restrict__ BB0,
             const float* __restrict__ BB2,
             const float* __restrict__ GS, const float* __restrict__ BB,
             const float* __restrict__ EW, const float* __restrict__ EB)
{
    extern __shared__ float sm[];
    int g = blockIdx.y;
    if (g == 0)
        tconv_body<COUT,CRES,MODE,GCONV,EMB,PSUM,5>(Zin,Yres,Yout,TWi,RWi,CST,BB0,BB2,GS,BB,EW,EB,0,sm);
    else if (g <= 2)
        tconv_body<COUT,CRES,MODE,GCONV,EMB,PSUM,6>(Zin,Yres,Yout,TWi,RWi,CST,BB0,BB2,GS,BB,EW,EB,g,sm);
    else
        tconv_body<COUT,CRES,MODE,GCONV,EMB,PSUM,4>(Zin,Yres,Yout,TWi,RWi,CST,BB0,BB2,GS,BB,EW,EB,g,sm);
}

// fused feature-mean (from psum) + VQ
__global__ __launch_bounds__(128) void k_featvq(const float* __restrict__ cb,
                                                float* __restrict__ out)
{
    int g = blockIdx.x, b = blockIdx.y;
    int tid = threadIdx.x;
    int n = c_gn[g];
    __shared__ float f[64];
    if (tid < 64){
        const float* pp = g_psum + (((size_t)g*64 + b)*16)*64 + tid;
        float s = 0.f;
        #pragma unroll
        for (int tile=0; tile<16; ++tile) s += pp[tile*64];
        f[tid] = s / (float)(NT*n);
    }
    __syncthreads();

    __shared__ float ds[128];
    __shared__ int   sidx;
    {
        const float* ck = cb + (g*128 + tid)*64;
        float dot=0.f, scb=0.f;
        for (int oo=0;oo<64;++oo){ dot += f[oo]*ck[oo]; scb += ck[oo]*ck[oo]; }
        ds[tid] = scb - 2.f*dot;
    }
    __syncthreads();
    if (tid==0){
        float best = ds[0]; int bi = 0;
        for (int kk=1;kk<128;++kk) if (ds[kk] < best){ best = ds[kk]; bi = kk; }
        sidx = bi;
    }
    __syncthreads();
    int idx = sidx;
    __shared__ float dsq[64];
    if (tid < 64){
        float q = cb[(g*128 + idx)*64 + tid];
        out[(g*64+b)*64 + tid] = q;
        float dd = q - f[tid];
        dsq[tid] = dd*dd;
    }
    __syncthreads();
    if (tid==0){
        float ss=0.f;
        for (int oo=0;oo<64;++oo) ss += dsq[oo];
        g_loss[g*64+b] = 1.25f * ss / 4096.f;
        out[5*64*64 + 1 + g*64 + b] = (float)idx;
    }
}

__global__ void k_lred(float* out){
    __shared__ float s[320];
    int t = threadIdx.x;
    if (t < 320) s[t] = g_loss[t];
    __syncthreads();
    if (t==0){
        float a=0.f;
        for (int i=0;i<320;i++) a += s[i];
        out[5*64*64] = a;
    }
}

extern "C" void kernel_launch(void* const* d_in, const int* in_sizes, int n_in,
                              void* d_out, int out_size)
{
    const float* x        = (const float*)d_in[0];
    const float* embed_w  = (const float*)d_in[1];
    const float* embed_b  = (const float*)d_in[2];
    const float* sgcn_w1  = (const float*)d_in[3];
    const float* sgcn_b1  = (const float*)d_in[4];
    const float* tconv_w1 = (const float*)d_in[5];
    const float* tconv_b1 = (const float*)d_in[6];
    const float* bn_g1    = (const float*)d_in[7];
    const float* bn_b1    = (const float*)d_in[8];
    const float* res_w2   = (const float*)d_in[9];
    const float* res_b2   = (const float*)d_in[10];
    const float* resbn_g2 = (const float*)d_in[11];
    const float* resbn_b2 = (const float*)d_in[12];
    const float* sgcn_w2  = (const float*)d_in[13];
    const float* sgcn_b2  = (const float*)d_in[14];
    const float* tconv_w2 = (const float*)d_in[15];
    const float* tconv_b2 = (const float*)d_in[16];
    const float* bn_g2    = (const float*)d_in[17];
    const float* bn_b2    = (const float*)d_in[18];
    const float* res_w3   = (const float*)d_in[19];
    const float* res_b3   = (const float*)d_in[20];
    const float* resbn_g3 = (const float*)d_in[21];
    const float* resbn_b3 = (const float*)d_in[22];
    const float* sgcn_w3  = (const float*)d_in[23];
    const float* sgcn_b3  = (const float*)d_in[24];
    const float* tconv_w3 = (const float*)d_in[25];
    const float* tconv_b3 = (const float*)d_in[26];
    const float* bn_g3    = (const float*)d_in[27];
    const float* bn_b3    = (const float*)d_in[28];
    const float* codebooks= (const float*)d_in[29];
    float* out = (float*)d_out;

    void *vp;
    #define SYM(name, s, T) cudaGetSymbolAddress(&vp, s); T* name = (T*)vp;
    SYM(pZ, g_Z, float)  SYM(pY1, g_Y1, float)
    SYM(pY2, g_Y2, float)  SYM(pY3, g_Y3, float)
    SYM(pSB3,g_sb3,float)
    SYM(pC1, g_cst1,float) SYM(pB01,g_bb0_1,float) SYM(pB21,g_bb2_1,float)
    SYM(pC2, g_cst2,float) SYM(pB02,g_bb0_2,float) SYM(pB22,g_bb2_2,float)
    SYM(pC3, g_cst3,float) SYM(pZERO,g_zero,float)
    SYM(pSW3,g_sw3i,float4)
    SYM(pRW2,g_rw2i,float4) SYM(pRW3,g_rw3i,float4)
    SYM(pTW1,g_tw1i,float4) SYM(pTW2,g_tw2i,float4) SYM(pTW3,g_tw3i,float4)
    #undef SYM

    dim3 grid16(BT/16, 5);

    size_t sm_t1 = (size_t)(18*6*17 + 1024)*16 + (18*6*3 + 192 + 64)*4;
    size_t sm_t2 = (size_t)(18*6*17 + 2048)*16;
    size_t sm_t3 = (size_t)(18*6*17 + 1024)*16;
    size_t sm_g3 = (size_t)(16*6*17 + 1024)*16;   // 42.6 KB

    cudaFuncSetAttribute((k_tconv<64,64,0,1,1,0>),   cudaFuncAttributeMaxDynamicSharedMemorySize, (int)sm_t1);
    cudaFuncSetAttribute((k_tconv<128,64,1,1,0,0>),  cudaFuncAttributeMaxDynamicSharedMemorySize, (int)sm_t2);
    cudaFuncSetAttribute(k_gcn3,                     cudaFuncAttributeMaxDynamicSharedMemorySize, (int)sm_g3);
    cudaFuncSetAttribute((k_tconv<64,128,1,0,0,1>),  cudaFuncAttributeMaxDynamicSharedMemorySize, (int)sm_t3);

    k_prep<<<64,256>>>(sgcn_w1, sgcn_b1, tconv_w1, tconv_b1,
                       res_w2, res_b2, resbn_g2, resbn_b2, sgcn_w2, sgcn_b2, tconv_w2, tconv_b2,
                       res_w3, res_b3, resbn_g3, resbn_b3, sgcn_w3, sgcn_b3, tconv_w3, tconv_b3);

    k_tconv<64,64,0,1,1,0><<<grid16,128,sm_t1>>>(x, x, pY1, pTW1, pRW2,
                                               pC1, pB01, pB21, bn_g1, bn_b1, embed_w, embed_b);
    k_tconv<128,64,1,1,0,0><<<grid16,256,sm_t2>>>(pY1, pY1, pY2, pTW2, pRW2,
                                                pC2, pB02, pB22, bn_g2, bn_b2, nullptr, nullptr);
    k_gcn3<<<grid16,128,sm_g3>>>(pY2, pZ, pSW3, pSB3);
    k_tconv<64,128,1,0,0,1><<<grid16,128,sm_t3>>>(pZ, pY2, pY3, pTW3, pRW3,
                                                pC3, pZERO, pZERO, bn_g3, bn_b3, nullptr, nullptr);

    k_featvq<<<dim3(5,64),128>>>(codebooks, out);
    k_lred<<<1,512>>>(out);
}